// round 5
// baseline (speedup 1.0000x reference)
#include <cuda_runtime.h>
#include <cuda_bf16.h>
#include <cstdint>

// Problem constants
#define D_DIA   128
#define L_DIA   40
#define NDIM    512
#define NHID    512
#define NUM_K   4
#define N_UTT   (D_DIA * L_DIA)        // 5120
#define N_NODE  (3 * N_UTT)            // 15360
#define ROWS_PER_DIA (3 * L_DIA)       // 120
#define OUT_D2  (NDIM + 2 * NHID)      // 1536
#define OUT_COLS (3 * OUT_D2)          // 4608

// GEMM config (mma.sync bf16, 3 fused precision passes)
#define BM 128
#define BN 128
#define BK 32                          // bf16 elems per k-tile (64 bytes)
#define KT_PER_PASS (NHID / BK)        // 16
#define KT_TOTAL (3 * KT_PER_PASS)     // 48
#define ROW_STRIDE 80                  // padded smem row stride (bytes) for 64B rows
#define TILE_BYTES (128 * ROW_STRIDE)  // 10240 per operand tile
#define STAGE_BYTES (2 * TILE_BYTES)   // 20480 (A + B)
#define STAGES 3
#define GEMM_SMEM_BYTES (STAGES * STAGE_BYTES)   // 61440

// ---------------------------------------------------------------------------
// Scratch (device globals; runtime allocation forbidden)
// ---------------------------------------------------------------------------
__device__ float g_feats[N_NODE * NDIM];
__device__ float g_x1   [N_NODE * NHID];
__device__ float g_bufA [N_NODE * NHID];
__device__ float g_bufB [N_NODE * NHID];
__device__ __nv_bfloat16 g_ahi[N_NODE * NHID];
__device__ __nv_bfloat16 g_alo[N_NODE * NHID];
__device__ __nv_bfloat16 g_wthi[5 * NHID * NHID];  // W^T: [w][n][k]
__device__ __nv_bfloat16 g_wtlo[5 * NHID * NHID];

// ---------------------------------------------------------------------------
// PTX helpers
// ---------------------------------------------------------------------------
__device__ __forceinline__ uint32_t smem_u32(const void* p) {
    uint32_t a;
    asm("{ .reg .u64 t; cvta.to.shared.u64 t, %1; cvt.u32.u64 %0, t; }" : "=r"(a) : "l"(p));
    return a;
}
__device__ __forceinline__ void cp16(uint32_t d, const void* g) {
    asm volatile("cp.async.cg.shared.global [%0], [%1], 16;" :: "r"(d), "l"(g));
}
__device__ __forceinline__ void ldsm4(uint32_t* r, uint32_t addr) {
    asm volatile("ldmatrix.sync.aligned.m8n8.x4.shared.b16 {%0,%1,%2,%3}, [%4];"
        : "=r"(r[0]), "=r"(r[1]), "=r"(r[2]), "=r"(r[3]) : "r"(addr));
}
__device__ __forceinline__ void mma_bf16(float* d, const uint32_t* a, uint32_t b0, uint32_t b1) {
    asm volatile("mma.sync.aligned.m16n8k16.row.col.f32.bf16.bf16.f32 "
        "{%0,%1,%2,%3}, {%4,%5,%6,%7}, {%8,%9}, {%0,%1,%2,%3};"
        : "+f"(d[0]), "+f"(d[1]), "+f"(d[2]), "+f"(d[3])
        : "r"(a[0]), "r"(a[1]), "r"(a[2]), "r"(a[3]), "r"(b0), "r"(b1));
}

// ---------------------------------------------------------------------------
// Weight transpose + hi/lo bf16 split: Wt[w][n][k] = W[w][k][n]
// ---------------------------------------------------------------------------
__global__ void transpose_split_kernel(const float* __restrict__ fc1W,
                                       const float* __restrict__ convW)
{
    __shared__ float tile[32][33];
    int w = blockIdx.z;
    const float* W = (w == 0) ? fc1W : convW + (size_t)(w - 1) * NHID * NHID;
    int n0 = blockIdx.x * 32, k0 = blockIdx.y * 32;
    #pragma unroll
    for (int i = 0; i < 32; i += 8)
        tile[threadIdx.y + i][threadIdx.x] = W[(size_t)(k0 + threadIdx.y + i) * NHID + n0 + threadIdx.x];
    __syncthreads();
    #pragma unroll
    for (int i = 0; i < 32; i += 8) {
        float v = tile[threadIdx.x][threadIdx.y + i];
        __nv_bfloat16 h = __float2bfloat16(v);
        size_t o = (size_t)w * NHID * NHID + (size_t)(n0 + threadIdx.y + i) * NHID + k0 + threadIdx.x;
        g_wthi[o] = h;
        g_wtlo[o] = __float2bfloat16(v - __bfloat162float(h));
    }
}

// ---------------------------------------------------------------------------
// Build node features (fp32 for assemble) + bf16 hi/lo split (GEMM A input)
// ---------------------------------------------------------------------------
__global__ void build_feats_kernel(const float* __restrict__ a,
                                   const float* __restrict__ v,
                                   const float* __restrict__ l,
                                   const float* __restrict__ qmask,
                                   const float* __restrict__ spk)
{
    int idx = blockIdx.x * blockDim.x + threadIdx.x;
    if (idx >= N_NODE * NDIM) return;
    int c    = idx & (NDIM - 1);
    int node = idx >> 9;
    int dia  = node / ROWS_PER_DIA;
    int r    = node - dia * ROWS_PER_DIA;
    int m    = r / L_DIA;
    int t    = r - m * L_DIA;
    int u    = dia * L_DIA + t;

    float val;
    if (m == 0) {
        float q0 = qmask[(t * D_DIA + dia) * 2 + 0];
        float q1 = qmask[(t * D_DIA + dia) * 2 + 1];
        int s = (q1 > q0) ? 1 : 0;
        val = l[u * NDIM + c] + spk[s * NDIM + c];
    } else if (m == 1) {
        val = a[u * NDIM + c];
    } else {
        val = v[u * NDIM + c];
    }
    g_feats[idx] = val;
    __nv_bfloat16 h = __float2bfloat16(val);
    g_ahi[idx] = h;
    g_alo[idx] = __float2bfloat16(val - __bfloat162float(h));
}

// ---------------------------------------------------------------------------
// Closed-form GCN aggregation fused with bf16 hi/lo split:
//   agg[dia,m,t] = (S[dia,m] + T[dia,t] - x[dia,m,t]) / 42
// ---------------------------------------------------------------------------
__global__ void agg_convert_kernel(const float* __restrict__ x)
{
    int dia = blockIdx.x;
    int c   = blockIdx.y * 128 + threadIdx.x;
    const float* xb = x + (size_t)dia * ROWS_PER_DIA * NHID;
    size_t ob = (size_t)dia * ROWS_PER_DIA * NHID;

    float S0 = 0.f, S1 = 0.f, S2 = 0.f;
    #pragma unroll 4
    for (int t = 0; t < L_DIA; t++) S0 += xb[t * NHID + c];
    #pragma unroll 4
    for (int t = 0; t < L_DIA; t++) S1 += xb[(L_DIA + t) * NHID + c];
    #pragma unroll 4
    for (int t = 0; t < L_DIA; t++) S2 += xb[(2 * L_DIA + t) * NHID + c];

    const float inv = 1.0f / 42.0f;
    for (int t = 0; t < L_DIA; t++) {
        float x0 = xb[t * NHID + c];
        float x1 = xb[(L_DIA + t) * NHID + c];
        float x2 = xb[(2 * L_DIA + t) * NHID + c];
        float T = x0 + x1 + x2;
        float v0 = (S0 + T - x0) * inv;
        float v1 = (S1 + T - x1) * inv;
        float v2 = (S2 + T - x2) * inv;
        size_t o0 = ob + (size_t)t * NHID + c;
        size_t o1 = ob + (size_t)(L_DIA + t) * NHID + c;
        size_t o2 = ob + (size_t)(2 * L_DIA + t) * NHID + c;
        __nv_bfloat16 h0 = __float2bfloat16(v0);
        __nv_bfloat16 h1 = __float2bfloat16(v1);
        __nv_bfloat16 h2 = __float2bfloat16(v2);
        g_ahi[o0] = h0; g_alo[o0] = __float2bfloat16(v0 - __bfloat162float(h0));
        g_ahi[o1] = h1; g_alo[o1] = __float2bfloat16(v1 - __bfloat162float(h1));
        g_ahi[o2] = h2; g_alo[o2] = __float2bfloat16(v2 - __bfloat162float(h2));
    }
}

// ---------------------------------------------------------------------------
// mma.sync bf16x3 GEMM: C[m,n] = sum_k A[m,k]*W[k,n] + bias[n] (+ P[m,n])
// A: hi/lo bf16 [M,512] row-major (g_ahi/g_alo); B: W^T hi/lo [512n][512k].
// Virtual K = 1536: pass0 Ahi*Bhi, pass1 Ahi*Blo, pass2 Alo*Bhi.
// ---------------------------------------------------------------------------
__global__ __launch_bounds__(256, 2)
void gemm_bf16x3_kernel(const __nv_bfloat16* __restrict__ Bhi,
                        const __nv_bfloat16* __restrict__ Blo,
                        const float* __restrict__ bias,
                        const float* __restrict__ P,
                        float* __restrict__ C)
{
    extern __shared__ char smem[];
    const uint32_t smem0 = smem_u32(smem);

    const int tid  = threadIdx.x;
    const int lane = tid & 31;
    const int wid  = tid >> 5;
    const int warp_m = wid & 3;        // 0..3 -> 32-row slab
    const int warp_n = wid >> 2;       // 0..1 -> 64-col slab
    const int bm = blockIdx.y * BM;
    const int bn = blockIdx.x * BN;

    float acc[2][8][4];
    #pragma unroll
    for (int i = 0; i < 2; i++)
        #pragma unroll
        for (int j = 0; j < 8; j++)
            #pragma unroll
            for (int q = 0; q < 4; q++) acc[i][j][q] = 0.f;

    // ldmatrix base addresses (stage 0, k16=0)
    const uint32_t aBase = smem0 + (uint32_t)(warp_m * 32 + (lane & 15)) * ROW_STRIDE
                         + (uint32_t)(lane >> 4) * 16;
    const uint32_t bBase = smem0 + TILE_BYTES
                         + (uint32_t)(warp_n * 64 + (lane & 15)) * ROW_STRIDE
                         + (uint32_t)(lane >> 4) * 16;

    const char* AhiP = (const char*)g_ahi;
    const char* AloP = (const char*)g_alo;
    const char* BhiP = (const char*)Bhi;
    const char* BloP = (const char*)Blo;

    auto load_tile = [&](int kt, int s) {
        int p = kt >> 4;
        const char* Ag = ((p < 2) ? AhiP : AloP) + (size_t)bm * 1024 + (kt & 15) * 64;
        const char* Bg = ((p == 1) ? BloP : BhiP) + (size_t)bn * 1024 + (kt & 15) * 64;
        uint32_t sa = smem0 + s * STAGE_BYTES;
        #pragma unroll
        for (int i = 0; i < 2; i++) {
            int ci  = i * 256 + tid;
            int row = ci >> 2;
            int cb  = (ci & 3) * 16;
            cp16(sa + row * ROW_STRIDE + cb, Ag + (size_t)row * 1024 + cb);
            cp16(sa + TILE_BYTES + row * ROW_STRIDE + cb, Bg + (size_t)row * 1024 + cb);
        }
        asm volatile("cp.async.commit_group;" ::: "memory");
    };

    // prologue: stages 0 and 1 in flight
    load_tile(0, 0);
    load_tile(1, 1);

    for (int kt = 0; kt < KT_TOTAL; kt++) {
        int s = kt % STAGES;
        asm volatile("cp.async.wait_group 1;" ::: "memory");
        __syncthreads();
        // keep one commit-group per iteration so wait_group 1 stays aligned
        if (kt + 2 < KT_TOTAL) load_tile(kt + 2, (kt + 2) % STAGES);
        else asm volatile("cp.async.commit_group;" ::: "memory");

        uint32_t sb = (uint32_t)s * STAGE_BYTES;
        #pragma unroll
        for (int k16 = 0; k16 < 2; k16++) {
            uint32_t a0[4], a1[4];
            ldsm4(a0, aBase + sb + k16 * 32);
            ldsm4(a1, aBase + sb + k16 * 32 + 16 * ROW_STRIDE);
            #pragma unroll
            for (int q = 0; q < 4; q++) {
                uint32_t b[4];
                ldsm4(b, bBase + sb + k16 * 32 + q * 16 * ROW_STRIDE);
                mma_bf16(acc[0][2 * q + 0], a0, b[0], b[2]);
                mma_bf16(acc[0][2 * q + 1], a0, b[1], b[3]);
                mma_bf16(acc[1][2 * q + 0], a1, b[0], b[2]);
                mma_bf16(acc[1][2 * q + 1], a1, b[1], b[3]);
            }
        }
    }

    // Epilogue: bias + optional residual, direct stores
    const bool hasP = (P != nullptr);
    const int m0 = bm + warp_m * 32;
    const int n0 = bn + warp_n * 64;
    #pragma unroll
    for (int mt = 0; mt < 2; mt++) {
        int r0 = m0 + mt * 16 + (lane >> 2);
        #pragma unroll
        for (int nt = 0; nt < 8; nt++) {
            int col = n0 + nt * 8 + (lane & 3) * 2;
            float bx = bias[col], by = bias[col + 1];
            size_t o0 = (size_t)r0 * NHID + col;
            size_t o1 = (size_t)(r0 + 8) * NHID + col;
            float2 v0 = make_float2(acc[mt][nt][0] + bx, acc[mt][nt][1] + by);
            float2 v1 = make_float2(acc[mt][nt][2] + bx, acc[mt][nt][3] + by);
            if (hasP) {
                float2 p0 = *(const float2*)(P + o0);
                float2 p1 = *(const float2*)(P + o1);
                v0.x += p0.x; v0.y += p0.y;
                v1.x += p1.x; v1.y += p1.y;
            }
            *(float2*)(C + o0) = v0;
            *(float2*)(C + o1) = v1;
        }
    }
}

// ---------------------------------------------------------------------------
// Assemble output: out[u, m*1536 + {feats|x1|gnn}]
// ---------------------------------------------------------------------------
__global__ void assemble_kernel(const float* __restrict__ gnn, float* __restrict__ out)
{
    int idx = blockIdx.x * blockDim.x + threadIdx.x;
    if (idx >= N_NODE * NDIM) return;
    int c    = idx & (NDIM - 1);
    int node = idx >> 9;
    int dia  = node / ROWS_PER_DIA;
    int r    = node - dia * ROWS_PER_DIA;
    int m    = r / L_DIA;
    int t    = r - m * L_DIA;
    int u    = dia * L_DIA + t;

    float* o = out + (size_t)u * OUT_COLS + m * OUT_D2 + c;
    o[0]        = g_feats[idx];
    o[NDIM]     = g_x1[idx];
    o[2 * NHID] = gnn[idx];
}

// ---------------------------------------------------------------------------
extern "C" void kernel_launch(void* const* d_in, const int* in_sizes, int n_in,
                              void* d_out, int out_size)
{
    const float* a      = (const float*)d_in[0];
    const float* v      = (const float*)d_in[1];
    const float* l      = (const float*)d_in[2];
    const float* qmask  = (const float*)d_in[3];
    const float* spk    = (const float*)d_in[4];
    const float* fc1_W  = (const float*)d_in[5];
    const float* fc1_b  = (const float*)d_in[6];
    const float* convW  = (const float*)d_in[7];
    const float* convb  = (const float*)d_in[8];
    float* out = (float*)d_out;

    float *x1 = nullptr, *bufA = nullptr, *bufB = nullptr;
    __nv_bfloat16 *wthi = nullptr, *wtlo = nullptr;
    cudaGetSymbolAddress((void**)&x1,   g_x1);
    cudaGetSymbolAddress((void**)&bufA, g_bufA);
    cudaGetSymbolAddress((void**)&bufB, g_bufB);
    cudaGetSymbolAddress((void**)&wthi, g_wthi);
    cudaGetSymbolAddress((void**)&wtlo, g_wtlo);

    cudaFuncSetAttribute(gemm_bf16x3_kernel,
                         cudaFuncAttributeMaxDynamicSharedMemorySize, GEMM_SMEM_BYTES);

    // 1. weights: transpose + bf16 split (w=0 fc1, w=1..4 conv)
    transpose_split_kernel<<<dim3(NHID / 32, NHID / 32, 5), dim3(32, 8)>>>(fc1_W, convW);

    // 2. features + bf16 split
    const int total = N_NODE * NDIM;
    build_feats_kernel<<<(total + 255) / 256, 256>>>(a, v, l, qmask, spk);

    dim3 gemm_grid(NHID / BN, N_NODE / BM);   // (4, 120)
    dim3 agg_grid(D_DIA, NHID / 128);         // (128, 4)

    // 3. x1 = feats @ fc1_W + fc1_b
    gemm_bf16x3_kernel<<<gemm_grid, 256, GEMM_SMEM_BYTES>>>(
        wthi, wtlo, fc1_b, nullptr, x1);

    // 4. gnn loop: gnn = gnn + agg(gnn) @ Wk + bk
    const float* cur = x1;
    float* nxt[4] = {bufA, bufB, bufA, bufB};
    for (int k = 0; k < NUM_K; k++) {
        agg_convert_kernel<<<agg_grid, 128>>>(cur);
        gemm_bf16x3_kernel<<<gemm_grid, 256, GEMM_SMEM_BYTES>>>(
            wthi + (size_t)(1 + k) * NHID * NHID,
            wtlo + (size_t)(1 + k) * NHID * NHID,
            convb + (size_t)k * NHID, cur, nxt[k]);
        cur = nxt[k];
    }

    // 5. assemble output
    assemble_kernel<<<(total + 255) / 256, 256>>>(cur, out);
    (void)in_sizes; (void)n_in; (void)out_size;
}

// round 6
// speedup vs baseline: 1.3036x; 1.3036x over previous
#include <cuda_runtime.h>
#include <cuda_bf16.h>
#include <cstdint>

#define D_DIA   128
#define L_DIA   40
#define NHID    512
#define N_UTT   5120
#define N_NODE  15360
#define ROWS_PER_DIA 120
#define OUT_D2  1536
#define OUT_COLS 4608
#define MM      (NHID * NHID)

// GEMM config (mma.sync bf16, 3 fused precision passes over K=512)
#define BM 128
#define BN 128
#define KT_TOTAL 48
#define ROW_STRIDE 80
#define TILE_BYTES (128 * ROW_STRIDE)
#define STAGE_BYTES (2 * TILE_BYTES)
#define GEMM_SMEM_BYTES (3 * STAGE_BYTES)

#define CHAIN_ROWS 2176     // M0(512) MB(512) MT(512) MG(512) d(128)
#define MEAN_ROWS  5632     // ft(5120) fb(384) fg(128)

// ---------------------------------------------------------------------------
// Device globals
// ---------------------------------------------------------------------------
__device__ float g_feats[N_NODE * NHID];
__device__ __nv_bfloat16 g_fahi[N_NODE * NHID], g_falo[N_NODE * NHID];
__device__ float g_x1[N_NODE * NHID];
__device__ __nv_bfloat16 g_x1hi[N_NODE * NHID], g_x1lo[N_NODE * NHID];
__device__ __nv_bfloat16 g_wthi[5 * MM], g_wtlo[5 * MM];      // B-format W^T
__device__ float g_chAf[CHAIN_ROWS * NHID], g_chBf[CHAIN_ROWS * NHID];
__device__ __nv_bfloat16 g_chAhi[CHAIN_ROWS * NHID], g_chAlo[CHAIN_ROWS * NHID];
__device__ __nv_bfloat16 g_chBhi[CHAIN_ROWS * NHID], g_chBlo[CHAIN_ROWS * NHID];
__device__ __nv_bfloat16 g_cbhi[4 * MM], g_cblo[4 * MM];      // combo B-splits
__device__ float g_means[MEAN_ROWS * NHID];
__device__ __nv_bfloat16 g_mhi[MEAN_ROWS * NHID], g_mlo[MEAN_ROWS * NHID];
__device__ float g_gnnA[N_NODE * NHID];
__device__ float g_gnnT[N_UTT * NHID];
__device__ float g_gnnB[512 * NHID];

// ---------------------------------------------------------------------------
// Helpers
// ---------------------------------------------------------------------------
__device__ __forceinline__ uint32_t smem_u32(const void* p) {
    uint32_t a;
    asm("{ .reg .u64 t; cvta.to.shared.u64 t, %1; cvt.u32.u64 %0, t; }" : "=r"(a) : "l"(p));
    return a;
}
__device__ __forceinline__ void cp16(uint32_t d, const void* g) {
    asm volatile("cp.async.cg.shared.global [%0], [%1], 16;" :: "r"(d), "l"(g));
}
__device__ __forceinline__ void ldsm4(uint32_t* r, uint32_t addr) {
    asm volatile("ldmatrix.sync.aligned.m8n8.x4.shared.b16 {%0,%1,%2,%3}, [%4];"
        : "=r"(r[0]), "=r"(r[1]), "=r"(r[2]), "=r"(r[3]) : "r"(addr));
}
__device__ __forceinline__ void mma_bf16(float* d, const uint32_t* a, uint32_t b0, uint32_t b1) {
    asm volatile("mma.sync.aligned.m16n8k16.row.col.f32.bf16.bf16.f32 "
        "{%0,%1,%2,%3}, {%4,%5,%6,%7}, {%8,%9}, {%0,%1,%2,%3};"
        : "+f"(d[0]), "+f"(d[1]), "+f"(d[2]), "+f"(d[3])
        : "r"(a[0]), "r"(a[1]), "r"(a[2]), "r"(a[3]), "r"(b0), "r"(b1));
}
__device__ __forceinline__ void split1(float v, __nv_bfloat16& h, __nv_bfloat16& l) {
    h = __float2bfloat16(v);
    l = __float2bfloat16(v - __bfloat162float(h));
}

// ---------------------------------------------------------------------------
// Unified GEMM (N=512): C = alpha_reg*(A*B) [+bias if y>=biasFromY] [+Pres]
// reg = min(blockIdx.y>>2, 4); B1 used when blockIdx.y >= b1FromY.
// ---------------------------------------------------------------------------
struct GP {
    const __nv_bfloat16 *Ahi, *Alo; int aofs;
    const __nv_bfloat16 *B0hi, *B0lo, *B1hi, *B1lo; int b1FromY;
    const float* bias; int biasFromY;
    const float* Pres;
    float alpha[5];
    float* C;
    __nv_bfloat16 *Chi, *Clo;
};

__global__ __launch_bounds__(256, 2)
void gemm_u(GP gp)
{
    extern __shared__ char smem[];
    const uint32_t smem0 = smem_u32(smem);
    const int tid  = threadIdx.x;
    const int lane = tid & 31;
    const int wid  = tid >> 5;
    const int warp_m = wid & 3, warp_n = wid >> 2;
    const int bm = blockIdx.y * BM, bn = blockIdx.x * BN;

    const bool useB1 = ((int)blockIdx.y >= gp.b1FromY);
    const __nv_bfloat16* Bhi = useB1 ? gp.B1hi : gp.B0hi;
    const __nv_bfloat16* Blo = useB1 ? gp.B1lo : gp.B0lo;
    int reg = blockIdx.y >> 2; if (reg > 4) reg = 4;
    const float alpha = gp.alpha[reg];
    const bool doBias = (gp.bias != nullptr) && ((int)blockIdx.y >= gp.biasFromY);

    float acc[2][8][4];
    #pragma unroll
    for (int i = 0; i < 2; i++)
        #pragma unroll
        for (int j = 0; j < 8; j++)
            #pragma unroll
            for (int q = 0; q < 4; q++) acc[i][j][q] = 0.f;

    const uint32_t aBase = smem0 + (uint32_t)(warp_m * 32 + (lane & 15)) * ROW_STRIDE
                         + (uint32_t)(lane >> 4) * 16;
    const uint32_t bBase = smem0 + TILE_BYTES
                         + (uint32_t)(warp_n * 64 + (lane & 15)) * ROW_STRIDE
                         + (uint32_t)(lane >> 4) * 16;

    const char* AhiP = (const char*)(gp.Ahi + (size_t)gp.aofs * NHID);
    const char* AloP = (const char*)(gp.Alo + (size_t)gp.aofs * NHID);
    const char* BhiP = (const char*)Bhi;
    const char* BloP = (const char*)Blo;

    auto load_tile = [&](int kt, int s) {
        int p = kt >> 4;
        const char* Ag = ((p < 2) ? AhiP : AloP) + (size_t)bm * 1024 + (kt & 15) * 64;
        const char* Bg = ((p == 1) ? BloP : BhiP) + (size_t)bn * 1024 + (kt & 15) * 64;
        uint32_t sa = smem0 + s * STAGE_BYTES;
        #pragma unroll
        for (int i = 0; i < 2; i++) {
            int ci  = i * 256 + tid;
            int row = ci >> 2;
            int cb  = (ci & 3) * 16;
            cp16(sa + row * ROW_STRIDE + cb, Ag + (size_t)row * 1024 + cb);
            cp16(sa + TILE_BYTES + row * ROW_STRIDE + cb, Bg + (size_t)row * 1024 + cb);
        }
        asm volatile("cp.async.commit_group;" ::: "memory");
    };

    load_tile(0, 0);
    load_tile(1, 1);

    for (int kt = 0; kt < KT_TOTAL; kt++) {
        int s = kt % 3;
        asm volatile("cp.async.wait_group 1;" ::: "memory");
        __syncthreads();
        if (kt + 2 < KT_TOTAL) load_tile(kt + 2, (kt + 2) % 3);
        else asm volatile("cp.async.commit_group;" ::: "memory");

        uint32_t sb = (uint32_t)s * STAGE_BYTES;
        #pragma unroll
        for (int k16 = 0; k16 < 2; k16++) {
            uint32_t a0[4], a1[4];
            ldsm4(a0, aBase + sb + k16 * 32);
            ldsm4(a1, aBase + sb + k16 * 32 + 16 * ROW_STRIDE);
            #pragma unroll
            for (int q = 0; q < 4; q++) {
                uint32_t b[4];
                ldsm4(b, bBase + sb + k16 * 32 + q * 16 * ROW_STRIDE);
                mma_bf16(acc[0][2 * q + 0], a0, b[0], b[2]);
                mma_bf16(acc[0][2 * q + 1], a0, b[1], b[3]);
                mma_bf16(acc[1][2 * q + 0], a1, b[0], b[2]);
                mma_bf16(acc[1][2 * q + 1], a1, b[1], b[3]);
            }
        }
    }

    const int m0 = bm + warp_m * 32;
    const int n0 = bn + warp_n * 64;
    #pragma unroll
    for (int mt = 0; mt < 2; mt++) {
        int r0 = m0 + mt * 16 + (lane >> 2);
        #pragma unroll
        for (int nt = 0; nt < 8; nt++) {
            int col = n0 + nt * 8 + (lane & 3) * 2;
            float2 v0 = make_float2(alpha * acc[mt][nt][0], alpha * acc[mt][nt][1]);
            float2 v1 = make_float2(alpha * acc[mt][nt][2], alpha * acc[mt][nt][3]);
            if (doBias) {
                float bx = gp.bias[col], by = gp.bias[col + 1];
                v0.x += bx; v0.y += by; v1.x += bx; v1.y += by;
            }
            size_t o0 = (size_t)r0 * NHID + col;
            size_t o1 = (size_t)(r0 + 8) * NHID + col;
            if (gp.Pres) {
                float2 p0 = *(const float2*)(gp.Pres + o0);
                float2 p1 = *(const float2*)(gp.Pres + o1);
                v0.x += p0.x; v0.y += p0.y; v1.x += p1.x; v1.y += p1.y;
            }
            *(float2*)(gp.C + o0) = v0;
            *(float2*)(gp.C + o1) = v1;
            if (gp.Chi) {
                __nv_bfloat16 h, l;
                split1(v0.x, h, l); gp.Chi[o0] = h;     gp.Clo[o0] = l;
                split1(v0.y, h, l); gp.Chi[o0 + 1] = h; gp.Clo[o0 + 1] = l;
                split1(v1.x, h, l); gp.Chi[o1] = h;     gp.Clo[o1] = l;
                split1(v1.y, h, l); gp.Chi[o1 + 1] = h; gp.Clo[o1 + 1] = l;
            }
        }
    }
}

// ---------------------------------------------------------------------------
// Weight transpose + split: wt[w][n][k] = W[w][k][n]  (w=0 fc1, 1..4 conv)
// ---------------------------------------------------------------------------
__global__ void transpose_split_kernel(const float* __restrict__ fc1W,
                                       const float* __restrict__ convW)
{
    __shared__ float tile[32][33];
    int w = blockIdx.z;
    const float* W = (w == 0) ? fc1W : convW + (size_t)(w - 1) * MM;
    int n0 = blockIdx.x * 32, k0 = blockIdx.y * 32;
    #pragma unroll
    for (int i = 0; i < 32; i += 8)
        tile[threadIdx.y + i][threadIdx.x] = W[(size_t)(k0 + threadIdx.y + i) * NHID + n0 + threadIdx.x];
    __syncthreads();
    #pragma unroll
    for (int i = 0; i < 32; i += 8) {
        size_t o = (size_t)w * MM + (size_t)(n0 + threadIdx.y + i) * NHID + k0 + threadIdx.x;
        split1(tile[threadIdx.x][threadIdx.y + i], g_wthi[o], g_wtlo[o]);
    }
}

// Chain init: rows 0-2047 = I + lam_j*convW0 (j = row>>9), rows 2048+ = convb0
__global__ void chain_init_kernel(const float* __restrict__ convW,
                                  const float* __restrict__ convb)
{
    int idx = blockIdx.x * blockDim.x + threadIdx.x;
    if (idx >= CHAIN_ROWS * NHID) return;
    int r = idx >> 9, c = idx & (NHID - 1);
    float v;
    if (r < 2048) {
        const float L[4] = { -1.f / 42.f, 39.f / 42.f, 2.f / 42.f, 1.f };
        int j = r >> 9, rr = r & (NHID - 1);
        v = L[j] * convW[(size_t)rr * NHID + c] + ((rr == c) ? 1.f : 0.f);
    } else {
        v = convb[c];
    }
    g_chAf[idx] = v;
    split1(v, g_chAhi[idx], g_chAlo[idx]);
}

// Transpose + combine chain result into 4 B-format matrices:
// z0: M0^T; z1: (MT-M0)^T; z2: (MB-M0)^T; z3: (M0-MB-MT+MG)^T
__global__ void combo_xpose_kernel()
{
    __shared__ float tile[32][33];
    const float CF[4][4] = { {1,0,0,0}, {-1,0,1,0}, {-1,1,0,0}, {1,-1,-1,1} };
    int z = blockIdx.z;
    int c0 = blockIdx.x * 32, r0 = blockIdx.y * 32;
    #pragma unroll
    for (int i = 0; i < 32; i += 8) {
        size_t rc = (size_t)(r0 + threadIdx.y + i) * NHID + c0 + threadIdx.x;
        float v = 0.f;
        #pragma unroll
        for (int j = 0; j < 4; j++)
            if (CF[z][j] != 0.f) v += CF[z][j] * g_chBf[(size_t)j * 512 * NHID + rc];
        tile[threadIdx.y + i][threadIdx.x] = v;
    }
    __syncthreads();
    #pragma unroll
    for (int i = 0; i < 32; i += 8) {
        size_t o = (size_t)z * MM + (size_t)(c0 + threadIdx.y + i) * NHID + r0 + threadIdx.x;
        split1(tile[threadIdx.x][threadIdx.y + i], g_cbhi[o], g_cblo[o]);
    }
}

// ---------------------------------------------------------------------------
// Build node features + splits
// ---------------------------------------------------------------------------
__global__ void build_feats_kernel(const float* __restrict__ a,
                                   const float* __restrict__ v,
                                   const float* __restrict__ l,
                                   const float* __restrict__ qmask,
                                   const float* __restrict__ spk)
{
    int idx = blockIdx.x * blockDim.x + threadIdx.x;   // N_NODE*128
    if (idx >= N_NODE * 128) return;
    int c    = (idx & 127) * 4;
    int node = idx >> 7;
    int dia  = node / ROWS_PER_DIA;
    int r    = node - dia * ROWS_PER_DIA;
    int m    = r / L_DIA;
    int t    = r - m * L_DIA;
    int u    = dia * L_DIA + t;

    float4 val;
    if (m == 0) {
        float q0 = qmask[(t * D_DIA + dia) * 2 + 0];
        float q1 = qmask[(t * D_DIA + dia) * 2 + 1];
        int s = (q1 > q0) ? 1 : 0;
        float4 lv = *(const float4*)(l + (size_t)u * NHID + c);
        float4 sv = *(const float4*)(spk + (size_t)s * NHID + c);
        val = make_float4(lv.x + sv.x, lv.y + sv.y, lv.z + sv.z, lv.w + sv.w);
    } else if (m == 1) {
        val = *(const float4*)(a + (size_t)u * NHID + c);
    } else {
        val = *(const float4*)(v + (size_t)u * NHID + c);
    }
    size_t o = (size_t)node * NHID + c;
    *(float4*)(g_feats + o) = val;
    split1(val.x, g_fahi[o],     g_falo[o]);
    split1(val.y, g_fahi[o + 1], g_falo[o + 1]);
    split1(val.z, g_fahi[o + 2], g_falo[o + 2]);
    split1(val.w, g_fahi[o + 3], g_falo[o + 3]);
}

// ---------------------------------------------------------------------------
// Means of x1: ft rows 0..5119, fb 5120..5503, fg 5504..5631 (f32 + splits)
// ---------------------------------------------------------------------------
__device__ __forceinline__ void store_mean4(size_t row, int c, float4 v)
{
    size_t o = row * NHID + c;
    *(float4*)(g_means + o) = v;
    split1(v.x, g_mhi[o],     g_mlo[o]);
    split1(v.y, g_mhi[o + 1], g_mlo[o + 1]);
    split1(v.z, g_mhi[o + 2], g_mlo[o + 2]);
    split1(v.w, g_mhi[o + 3], g_mlo[o + 3]);
}

__global__ void means_kernel()
{
    int dia = blockIdx.x;
    int c   = threadIdx.x * 4;
    const float* xb = g_x1 + (size_t)dia * ROWS_PER_DIA * NHID;

    float4 b0 = make_float4(0, 0, 0, 0), b1 = b0, b2 = b0;
    for (int t = 0; t < L_DIA; t++) {
        float4 v0 = *(const float4*)(xb + (size_t)t * NHID + c);
        float4 v1 = *(const float4*)(xb + (size_t)(L_DIA + t) * NHID + c);
        float4 v2 = *(const float4*)(xb + (size_t)(2 * L_DIA + t) * NHID + c);
        b0.x += v0.x; b0.y += v0.y; b0.z += v0.z; b0.w += v0.w;
        b1.x += v1.x; b1.y += v1.y; b1.z += v1.z; b1.w += v1.w;
        b2.x += v2.x; b2.y += v2.y; b2.z += v2.z; b2.w += v2.w;
        const float i3 = 1.f / 3.f;
        store_mean4((size_t)dia * L_DIA + t, c,
            make_float4((v0.x + v1.x + v2.x) * i3, (v0.y + v1.y + v2.y) * i3,
                        (v0.z + v1.z + v2.z) * i3, (v0.w + v1.w + v2.w) * i3));
    }
    const float i40 = 1.f / 40.f, i120 = 1.f / 120.f;
    store_mean4(5120 + (size_t)dia * 3 + 0, c, make_float4(b0.x * i40, b0.y * i40, b0.z * i40, b0.w * i40));
    store_mean4(5120 + (size_t)dia * 3 + 1, c, make_float4(b1.x * i40, b1.y * i40, b1.z * i40, b1.w * i40));
    store_mean4(5120 + (size_t)dia * 3 + 2, c, make_float4(b2.x * i40, b2.y * i40, b2.z * i40, b2.w * i40));
    store_mean4(5504 + (size_t)dia, c,
        make_float4((b0.x + b1.x + b2.x) * i120, (b0.y + b1.y + b2.y) * i120,
                    (b0.z + b1.z + b2.z) * i120, (b0.w + b1.w + b2.w) * i120));
}

// ---------------------------------------------------------------------------
// Combine + assemble: gnn = gnnA + gnnT[dia,t] + gnnB_fb[dia,m] + gnnB_fg[dia] + d
// ---------------------------------------------------------------------------
__global__ void combine_kernel(float* __restrict__ out)
{
    int idx = blockIdx.x * blockDim.x + threadIdx.x;
    if (idx >= N_NODE * 128) return;
    int c    = (idx & 127) * 4;
    int node = idx >> 7;
    int dia  = node / ROWS_PER_DIA;
    int r    = node - dia * ROWS_PER_DIA;
    int m    = r / L_DIA;
    int t    = r - m * L_DIA;
    int u    = dia * L_DIA + t;

    float4 f  = *(const float4*)(g_feats + (size_t)node * NHID + c);
    float4 x1 = *(const float4*)(g_x1 + (size_t)node * NHID + c);
    float4 ga = *(const float4*)(g_gnnA + (size_t)node * NHID + c);
    float4 gt = *(const float4*)(g_gnnT + ((size_t)dia * L_DIA + t) * NHID + c);
    float4 gb = *(const float4*)(g_gnnB + ((size_t)dia * 3 + m) * NHID + c);
    float4 gg = *(const float4*)(g_gnnB + (size_t)(384 + dia) * NHID + c);
    float4 dd = *(const float4*)(g_chBf + (size_t)2048 * NHID + c);

    float4 gnn = make_float4(ga.x + gt.x + gb.x + gg.x + dd.x,
                             ga.y + gt.y + gb.y + gg.y + dd.y,
                             ga.z + gt.z + gb.z + gg.z + dd.z,
                             ga.w + gt.w + gb.w + gg.w + dd.w);

    float* o = out + (size_t)u * OUT_COLS + m * OUT_D2 + c;
    *(float4*)(o)        = f;
    *(float4*)(o + 512)  = x1;
    *(float4*)(o + 1024) = gnn;
}

// ---------------------------------------------------------------------------
extern "C" void kernel_launch(void* const* d_in, const int* in_sizes, int n_in,
                              void* d_out, int out_size)
{
    const float* a      = (const float*)d_in[0];
    const float* v      = (const float*)d_in[1];
    const float* l      = (const float*)d_in[2];
    const float* qmask  = (const float*)d_in[3];
    const float* spk    = (const float*)d_in[4];
    const float* fc1_W  = (const float*)d_in[5];
    const float* fc1_b  = (const float*)d_in[6];
    const float* convW  = (const float*)d_in[7];
    const float* convb  = (const float*)d_in[8];
    float* out = (float*)d_out;

    __nv_bfloat16 *wthi, *wtlo, *fahi, *falo, *x1hi, *x1lo, *mhi, *mlo, *cbhi, *cblo;
    __nv_bfloat16 *chAhi, *chAlo, *chBhi, *chBlo;
    float *x1, *chAf, *chBf, *gnnA, *gnnT, *gnnB;
    cudaGetSymbolAddress((void**)&wthi, g_wthi);   cudaGetSymbolAddress((void**)&wtlo, g_wtlo);
    cudaGetSymbolAddress((void**)&fahi, g_fahi);   cudaGetSymbolAddress((void**)&falo, g_falo);
    cudaGetSymbolAddress((void**)&x1,   g_x1);
    cudaGetSymbolAddress((void**)&x1hi, g_x1hi);   cudaGetSymbolAddress((void**)&x1lo, g_x1lo);
    cudaGetSymbolAddress((void**)&mhi,  g_mhi);    cudaGetSymbolAddress((void**)&mlo,  g_mlo);
    cudaGetSymbolAddress((void**)&cbhi, g_cbhi);   cudaGetSymbolAddress((void**)&cblo, g_cblo);
    cudaGetSymbolAddress((void**)&chAhi, g_chAhi); cudaGetSymbolAddress((void**)&chAlo, g_chAlo);
    cudaGetSymbolAddress((void**)&chBhi, g_chBhi); cudaGetSymbolAddress((void**)&chBlo, g_chBlo);
    cudaGetSymbolAddress((void**)&chAf, g_chAf);   cudaGetSymbolAddress((void**)&chBf, g_chBf);
    cudaGetSymbolAddress((void**)&gnnA, g_gnnA);
    cudaGetSymbolAddress((void**)&gnnT, g_gnnT);
    cudaGetSymbolAddress((void**)&gnnB, g_gnnB);

    cudaFuncSetAttribute(gemm_u, cudaFuncAttributeMaxDynamicSharedMemorySize, GEMM_SMEM_BYTES);

    auto mk = [&]() {
        GP p{};
        p.b1FromY = 1 << 20;
        p.biasFromY = 1 << 20;
        for (int i = 0; i < 5; i++) p.alpha[i] = 1.f;
        return p;
    };

    // 1. weight prep + chain init
    transpose_split_kernel<<<dim3(16, 16, 5), dim3(32, 8)>>>(fc1_W, convW);
    chain_init_kernel<<<(CHAIN_ROWS * NHID + 255) / 256, 256>>>(convW, convb);

    // 2. chain steps k=2,3,4: X <- X + lam_reg*(X*Wk) (+bk for d region)
    {
        float* srcF[2] = { chAf, chBf };
        __nv_bfloat16* sH[2] = { chAhi, chBhi };
        __nv_bfloat16* sL[2] = { chAlo, chBlo };
        for (int k = 2; k <= 4; k++) {
            int s = k & 1;           // k=2: src A(0), k=3: src B(1), k=4: src A(0)
            int d = s ^ 1;
            GP p = mk();
            p.Ahi = sH[s]; p.Alo = sL[s]; p.aofs = 0;
            p.B0hi = wthi + (size_t)k * MM; p.B0lo = wtlo + (size_t)k * MM;
            p.bias = convb + (size_t)(k - 1) * NHID; p.biasFromY = 16;
            p.Pres = srcF[s];
            p.alpha[0] = -1.f / 42.f; p.alpha[1] = 39.f / 42.f;
            p.alpha[2] = 2.f / 42.f;  p.alpha[3] = 1.f; p.alpha[4] = 1.f;
            p.C = srcF[d]; p.Chi = sH[d]; p.Clo = sL[d];
            gemm_u<<<dim3(4, CHAIN_ROWS / 128), 256, GEMM_SMEM_BYTES>>>(p);
        }
    }
    // final chain (after k=4) lives in chB
    combo_xpose_kernel<<<dim3(16, 16, 4), dim3(32, 8)>>>();

    // 3. features + x1 GEMM
    build_feats_kernel<<<(N_NODE * 128 + 255) / 256, 256>>>(a, v, l, qmask, spk);
    {
        GP p = mk();
        p.Ahi = fahi; p.Alo = falo; p.aofs = 0;
        p.B0hi = wthi; p.B0lo = wtlo;
        p.bias = fc1_b; p.biasFromY = 0;
        p.C = x1; p.Chi = x1hi; p.Clo = x1lo;
        gemm_u<<<dim3(4, N_NODE / 128), 256, GEMM_SMEM_BYTES>>>(p);
    }
    means_kernel<<<D_DIA, 128>>>();

    // 4. gnnA = x1 * M0
    {
        GP p = mk();
        p.Ahi = x1hi; p.Alo = x1lo; p.aofs = 0;
        p.B0hi = cbhi; p.B0lo = cblo;
        p.C = gnnA;
        gemm_u<<<dim3(4, N_NODE / 128), 256, GEMM_SMEM_BYTES>>>(p);
    }
    // 5. gnnT = ft * (MT - M0)
    {
        GP p = mk();
        p.Ahi = mhi; p.Alo = mlo; p.aofs = 0;
        p.B0hi = cbhi + MM; p.B0lo = cblo + MM;
        p.C = gnnT;
        gemm_u<<<dim3(4, N_UTT / 128), 256, GEMM_SMEM_BYTES>>>(p);
    }
    // 6. gnnB: rows 0-383 fb*(MB-M0); rows 384-511 fg*(M0-MB-MT+MG)
    {
        GP p = mk();
        p.Ahi = mhi; p.Alo = mlo; p.aofs = 5120;
        p.B0hi = cbhi + 2 * (size_t)MM; p.B0lo = cblo + 2 * (size_t)MM;
        p.B1hi = cbhi + 3 * (size_t)MM; p.B1lo = cblo + 3 * (size_t)MM;
        p.b1FromY = 3;
        p.C = gnnB;
        gemm_u<<<dim3(4, 4), 256, GEMM_SMEM_BYTES>>>(p);
    }

    // 7. combine + assemble
    combine_kernel<<<(N_NODE * 128 + 255) / 256, 256>>>(out);
    (void)in_sizes; (void)n_in; (void)out_size;
}

// round 8
// speedup vs baseline: 1.7481x; 1.3410x over previous
#include <cuda_runtime.h>
#include <cuda_bf16.h>
#include <cstdint>

#define D_DIA   128
#define L_DIA   40
#define NHID    512
#define N_UTT   5120
#define N_NODE  15360
#define ROWS_PER_DIA 120
#define OUT_D2  1536
#define OUT_COLS 4608
#define MM      (NHID * NHID)

// GEMM config: BK=64 elems (128B), XOR-swizzled rows, 3 precision passes
#define BM 128
#define BN 128
#define KT_TOTAL 24                    // 3 passes x 8 k-tiles
#define TILE_BYTES (128 * 128)         // 16 KB per operand tile
#define STAGE_BYTES (2 * TILE_BYTES)   // 32 KB
#define GEMM_SMEM_BYTES (3 * STAGE_BYTES)  // 96 KB

#define CHAIN_ROWS 2176     // M0(512) MB(512) MT(512) MG(512) d(128)
#define MEAN_ROWS  5632     // ft(5120) fb(384) fg(128)
#define GNN_ROWS   20992    // gnnA(15360) ft-out(5120) fb-out(384) fg-out(128)

// ---------------------------------------------------------------------------
// Device globals
// ---------------------------------------------------------------------------
__device__ float g_feats[N_NODE * NHID];
__device__ __nv_bfloat16 g_fahi[N_NODE * NHID], g_falo[N_NODE * NHID];
__device__ float g_x1[N_NODE * NHID];
__device__ __nv_bfloat16 g_x1hi[N_NODE * NHID], g_x1lo[N_NODE * NHID];
__device__ __nv_bfloat16 g_wthi[5 * MM], g_wtlo[5 * MM];
__device__ float g_chAf[CHAIN_ROWS * NHID], g_chBf[CHAIN_ROWS * NHID];
__device__ __nv_bfloat16 g_chAhi[CHAIN_ROWS * NHID], g_chAlo[CHAIN_ROWS * NHID];
__device__ __nv_bfloat16 g_chBhi[CHAIN_ROWS * NHID], g_chBlo[CHAIN_ROWS * NHID];
__device__ __nv_bfloat16 g_cbhi[4 * MM], g_cblo[4 * MM];
__device__ float g_means[MEAN_ROWS * NHID];
__device__ __nv_bfloat16 g_mhi[MEAN_ROWS * NHID], g_mlo[MEAN_ROWS * NHID];
__device__ float g_gnn[GNN_ROWS * NHID];

// ---------------------------------------------------------------------------
// Helpers
// ---------------------------------------------------------------------------
__device__ __forceinline__ uint32_t smem_u32(const void* p) {
    uint32_t a;
    asm("{ .reg .u64 t; cvta.to.shared.u64 t, %1; cvt.u32.u64 %0, t; }" : "=r"(a) : "l"(p));
    return a;
}
__device__ __forceinline__ void cp16(uint32_t d, const void* g) {
    asm volatile("cp.async.cg.shared.global [%0], [%1], 16;" :: "r"(d), "l"(g));
}
__device__ __forceinline__ void ldsm4(uint32_t* r, uint32_t addr) {
    asm volatile("ldmatrix.sync.aligned.m8n8.x4.shared.b16 {%0,%1,%2,%3}, [%4];"
        : "=r"(r[0]), "=r"(r[1]), "=r"(r[2]), "=r"(r[3]) : "r"(addr));
}
__device__ __forceinline__ void mma_bf16(float* d, const uint32_t* a, uint32_t b0, uint32_t b1) {
    asm volatile("mma.sync.aligned.m16n8k16.row.col.f32.bf16.bf16.f32 "
        "{%0,%1,%2,%3}, {%4,%5,%6,%7}, {%8,%9}, {%0,%1,%2,%3};"
        : "+f"(d[0]), "+f"(d[1]), "+f"(d[2]), "+f"(d[3])
        : "r"(a[0]), "r"(a[1]), "r"(a[2]), "r"(a[3]), "r"(b0), "r"(b1));
}
__device__ __forceinline__ void split1(float v, __nv_bfloat16& h, __nv_bfloat16& l) {
    h = __float2bfloat16(v);
    l = __float2bfloat16(v - __bfloat162float(h));
}

// ---------------------------------------------------------------------------
// Unified GEMM with per-y-region dispatch (5 regions):
//   region = max i with blockIdx.y >= yStart[i]
//   C = alpha[reg]*(A*B[reg]) [+bias[reg]] [+Pres]
// A switches to (Ahi1,Alo1) with row -= aRowOfs1 when blockIdx.y >= aSwitchY.
// ---------------------------------------------------------------------------
struct GP {
    const __nv_bfloat16 *Ahi0, *Alo0, *Ahi1, *Alo1;
    int aSwitchY, aRowOfs1;
    const __nv_bfloat16 *Bhi[5], *Blo[5];
    const float* bias[5];
    float alpha[5];
    int yStart[5];
    const float* Pres;
    float* C;
    __nv_bfloat16 *Chi, *Clo;
};

__global__ __launch_bounds__(256, 2)
void gemm_u(GP gp)
{
    extern __shared__ char smem[];
    const uint32_t smem0 = smem_u32(smem);
    const int tid  = threadIdx.x;
    const int lane = tid & 31;
    const int wid  = tid >> 5;
    const int warp_m = wid & 3, warp_n = wid >> 2;
    const int bm = blockIdx.y * BM, bn = blockIdx.x * BN;

    int reg = 0;
    #pragma unroll
    for (int i = 1; i < 5; i++) if ((int)blockIdx.y >= gp.yStart[i]) reg = i;
    const float alpha = gp.alpha[reg];
    const float* bias = gp.bias[reg];

    const __nv_bfloat16* Ahi = gp.Ahi0;
    const __nv_bfloat16* Alo = gp.Alo0;
    int arow = bm;
    if ((int)blockIdx.y >= gp.aSwitchY) { Ahi = gp.Ahi1; Alo = gp.Alo1; arow = bm - gp.aRowOfs1; }

    float acc[2][8][4];
    #pragma unroll
    for (int i = 0; i < 2; i++)
        #pragma unroll
        for (int j = 0; j < 8; j++)
            #pragma unroll
            for (int q = 0; q < 4; q++) acc[i][j][q] = 0.f;

    const char* AhiP = (const char*)Ahi + (size_t)arow * 1024;
    const char* AloP = (const char*)Alo + (size_t)arow * 1024;
    const char* BhiP = (const char*)gp.Bhi[reg] + (size_t)bn * 1024;
    const char* BloP = (const char*)gp.Blo[reg] + (size_t)bn * 1024;

    auto load_tile = [&](int kt, int s) {
        int p = kt >> 3;
        const char* Ag = ((p < 2) ? AhiP : AloP) + (kt & 7) * 128;
        const char* Bg = ((p == 1) ? BloP : BhiP) + (kt & 7) * 128;
        uint32_t sa = smem0 + s * STAGE_BYTES;
        #pragma unroll
        for (int i = 0; i < 4; i++) {
            int ci  = i * 256 + tid;          // 0..1023
            int row = ci >> 3;
            int c16 = ci & 7;
            uint32_t so = (uint32_t)row * 128 + (uint32_t)(((c16 ^ (row & 7))) * 16);
            cp16(sa + so, Ag + (size_t)row * 1024 + c16 * 16);
            cp16(sa + TILE_BYTES + so, Bg + (size_t)row * 1024 + c16 * 16);
        }
        asm volatile("cp.async.commit_group;" ::: "memory");
    };

    // per-thread ldmatrix address components
    const int half = lane >> 4;                 // 0/1: 16B half within 32B k16
    const int lx   = lane & 7;                  // XOR swizzle term (row & 7)
    const uint32_t aOff = (uint32_t)(warp_m * 32 + (lane & 15)) * 128;
    const uint32_t bOff = (uint32_t)(warp_n * 64 + (lane & 15)) * 128;

    load_tile(0, 0);
    load_tile(1, 1);

    for (int kt = 0; kt < KT_TOTAL; kt++) {
        int s = kt % 3;
        asm volatile("cp.async.wait_group 1;" ::: "memory");
        __syncthreads();
        if (kt + 2 < KT_TOTAL) load_tile(kt + 2, (kt + 2) % 3);
        else asm volatile("cp.async.commit_group;" ::: "memory");

        const uint32_t sbase = smem0 + (uint32_t)s * STAGE_BYTES;
        #pragma unroll
        for (int k16 = 0; k16 < 4; k16++) {
            const uint32_t co = (uint32_t)(((2 * k16 + half) ^ lx) * 16);
            uint32_t a0[4], a1[4];
            ldsm4(a0, sbase + aOff + co);
            ldsm4(a1, sbase + aOff + 2048 + co);
            #pragma unroll
            for (int q = 0; q < 4; q++) {
                uint32_t b[4];
                ldsm4(b, sbase + TILE_BYTES + bOff + (uint32_t)q * 2048 + co);
                mma_bf16(acc[0][2 * q + 0], a0, b[0], b[2]);
                mma_bf16(acc[0][2 * q + 1], a0, b[1], b[3]);
                mma_bf16(acc[1][2 * q + 0], a1, b[0], b[2]);
                mma_bf16(acc[1][2 * q + 1], a1, b[1], b[3]);
            }
        }
    }

    const int m0 = bm + warp_m * 32;
    const int n0 = bn + warp_n * 64;
    #pragma unroll
    for (int mt = 0; mt < 2; mt++) {
        int r0 = m0 + mt * 16 + (lane >> 2);
        #pragma unroll
        for (int nt = 0; nt < 8; nt++) {
            int col = n0 + nt * 8 + (lane & 3) * 2;
            float2 v0 = make_float2(alpha * acc[mt][nt][0], alpha * acc[mt][nt][1]);
            float2 v1 = make_float2(alpha * acc[mt][nt][2], alpha * acc[mt][nt][3]);
            if (bias) {
                float bx = bias[col], by = bias[col + 1];
                v0.x += bx; v0.y += by; v1.x += bx; v1.y += by;
            }
            size_t o0 = (size_t)r0 * NHID + col;
            size_t o1 = (size_t)(r0 + 8) * NHID + col;
            if (gp.Pres) {
                float2 p0 = *(const float2*)(gp.Pres + o0);
                float2 p1 = *(const float2*)(gp.Pres + o1);
                v0.x += p0.x; v0.y += p0.y; v1.x += p1.x; v1.y += p1.y;
            }
            *(float2*)(gp.C + o0) = v0;
            *(float2*)(gp.C + o1) = v1;
            if (gp.Chi) {
                __nv_bfloat16 h, l;
                split1(v0.x, h, l); gp.Chi[o0] = h;     gp.Clo[o0] = l;
                split1(v0.y, h, l); gp.Chi[o0 + 1] = h; gp.Clo[o0 + 1] = l;
                split1(v1.x, h, l); gp.Chi[o1] = h;     gp.Clo[o1] = l;
                split1(v1.y, h, l); gp.Chi[o1 + 1] = h; gp.Clo[o1 + 1] = l;
            }
        }
    }
}

// ---------------------------------------------------------------------------
// Weight transpose + split: wt[w][n][k] = W[w][k][n]  (w=0 fc1, 1..4 conv)
// ---------------------------------------------------------------------------
__global__ void transpose_split_kernel(const float* __restrict__ fc1W,
                                       const float* __restrict__ convW)
{
    __shared__ float tile[32][33];
    int w = blockIdx.z;
    const float* W = (w == 0) ? fc1W : convW + (size_t)(w - 1) * MM;
    int n0 = blockIdx.x * 32, k0 = blockIdx.y * 32;
    #pragma unroll
    for (int i = 0; i < 32; i += 8)
        tile[threadIdx.y + i][threadIdx.x] = W[(size_t)(k0 + threadIdx.y + i) * NHID + n0 + threadIdx.x];
    __syncthreads();
    #pragma unroll
    for (int i = 0; i < 32; i += 8) {
        size_t o = (size_t)w * MM + (size_t)(n0 + threadIdx.y + i) * NHID + k0 + threadIdx.x;
        split1(tile[threadIdx.x][threadIdx.y + i], g_wthi[o], g_wtlo[o]);
    }
}

// Chain init: rows 0-2047 = I + lam_j*convW0 (j = row>>9), rows 2048+ = convb0
__global__ void chain_init_kernel(const float* __restrict__ convW,
                                  const float* __restrict__ convb)
{
    int idx = blockIdx.x * blockDim.x + threadIdx.x;
    if (idx >= CHAIN_ROWS * NHID) return;
    int r = idx >> 9, c = idx & (NHID - 1);
    float v;
    if (r < 2048) {
        const float L[4] = { -1.f / 42.f, 39.f / 42.f, 2.f / 42.f, 1.f };
        int j = r >> 9, rr = r & (NHID - 1);
        v = L[j] * convW[(size_t)rr * NHID + c] + ((rr == c) ? 1.f : 0.f);
    } else {
        v = convb[c];
    }
    g_chAf[idx] = v;
    split1(v, g_chAhi[idx], g_chAlo[idx]);
}

// Transpose + combine chain result into 4 B-format matrices:
// z0: M0^T; z1: (MT-M0)^T; z2: (MB-M0)^T; z3: (M0-MB-MT+MG)^T
__global__ void combo_xpose_kernel()
{
    __shared__ float tile[32][33];
    const float CF[4][4] = { {1,0,0,0}, {-1,0,1,0}, {-1,1,0,0}, {1,-1,-1,1} };
    int z = blockIdx.z;
    int c0 = blockIdx.x * 32, r0 = blockIdx.y * 32;
    #pragma unroll
    for (int i = 0; i < 32; i += 8) {
        size_t rc = (size_t)(r0 + threadIdx.y + i) * NHID + c0 + threadIdx.x;
        float v = 0.f;
        #pragma unroll
        for (int j = 0; j < 4; j++)
            if (CF[z][j] != 0.f) v += CF[z][j] * g_chBf[(size_t)j * 512 * NHID + rc];
        tile[threadIdx.y + i][threadIdx.x] = v;
    }
    __syncthreads();
    #pragma unroll
    for (int i = 0; i < 32; i += 8) {
        size_t o = (size_t)z * MM + (size_t)(c0 + threadIdx.y + i) * NHID + r0 + threadIdx.x;
        split1(tile[threadIdx.x][threadIdx.y + i], g_cbhi[o], g_cblo[o]);
    }
}

// ---------------------------------------------------------------------------
// Build node features + splits
// ---------------------------------------------------------------------------
__global__ void build_feats_kernel(const float* __restrict__ a,
                                   const float* __restrict__ v,
                                   const float* __restrict__ l,
                                   const float* __restrict__ qmask,
                                   const float* __restrict__ spk)
{
    int idx = blockIdx.x * blockDim.x + threadIdx.x;
    if (idx >= N_NODE * 128) return;
    int c    = (idx & 127) * 4;
    int node = idx >> 7;
    int dia  = node / ROWS_PER_DIA;
    int r    = node - dia * ROWS_PER_DIA;
    int m    = r / L_DIA;
    int t    = r - m * L_DIA;
    int u    = dia * L_DIA + t;

    float4 val;
    if (m == 0) {
        float q0 = qmask[(t * D_DIA + dia) * 2 + 0];
        float q1 = qmask[(t * D_DIA + dia) * 2 + 1];
        int s = (q1 > q0) ? 1 : 0;
        float4 lv = *(const float4*)(l + (size_t)u * NHID + c);
        float4 sv = *(const float4*)(spk + (size_t)s * NHID + c);
        val = make_float4(lv.x + sv.x, lv.y + sv.y, lv.z + sv.z, lv.w + sv.w);
    } else if (m == 1) {
        val = *(const float4*)(a + (size_t)u * NHID + c);
    } else {
        val = *(const float4*)(v + (size_t)u * NHID + c);
    }
    size_t o = (size_t)node * NHID + c;
    *(float4*)(g_feats + o) = val;
    split1(val.x, g_fahi[o],     g_falo[o]);
    split1(val.y, g_fahi[o + 1], g_falo[o + 1]);
    split1(val.z, g_fahi[o + 2], g_falo[o + 2]);
    split1(val.w, g_fahi[o + 3], g_falo[o + 3]);
}

// ---------------------------------------------------------------------------
// Means of x1: ft rows 0..5119, fb 5120..5503, fg 5504..5631 (f32 + splits)
// ---------------------------------------------------------------------------
__device__ __forceinline__ void store_mean4(size_t row, int c, float4 v)
{
    size_t o = row * NHID + c;
    *(float4*)(g_means + o) = v;
    split1(v.x, g_mhi[o],     g_mlo[o]);
    split1(v.y, g_mhi[o + 1], g_mlo[o + 1]);
    split1(v.z, g_mhi[o + 2], g_mlo[o + 2]);
    split1(v.w, g_mhi[o + 3], g_mlo[o + 3]);
}

__global__ void means_kernel()
{
    int dia = blockIdx.x;
    int c   = threadIdx.x * 4;
    const float* xb = g_x1 + (size_t)dia * ROWS_PER_DIA * NHID;

    float4 b0 = make_float4(0, 0, 0, 0), b1 = b0, b2 = b0;
    for (int t = 0; t < L_DIA; t++) {
        float4 v0 = *(const float4*)(xb + (size_t)t * NHID + c);
        float4 v1 = *(const float4*)(xb + (size_t)(L_DIA + t) * NHID + c);
        float4 v2 = *(const float4*)(xb + (size_t)(2 * L_DIA + t) * NHID + c);
        b0.x += v0.x; b0.y += v0.y; b0.z += v0.z; b0.w += v0.w;
        b1.x += v1.x; b1.y += v1.y; b1.z += v1.z; b1.w += v1.w;
        b2.x += v2.x; b2.y += v2.y; b2.z += v2.z; b2.w += v2.w;
        const float i3 = 1.f / 3.f;
        store_mean4((size_t)dia * L_DIA + t, c,
            make_float4((v0.x + v1.x + v2.x) * i3, (v0.y + v1.y + v2.y) * i3,
                        (v0.z + v1.z + v2.z) * i3, (v0.w + v1.w + v2.w) * i3));
    }
    const float i40 = 1.f / 40.f, i120 = 1.f / 120.f;
    store_mean4(5120 + (size_t)dia * 3 + 0, c, make_float4(b0.x * i40, b0.y * i40, b0.z * i40, b0.w * i40));
    store_mean4(5120 + (size_t)dia * 3 + 1, c, make_float4(b1.x * i40, b1.y * i40, b1.z * i40, b1.w * i40));
    store_mean4(5120 + (size_t)dia * 3 + 2, c, make_float4(b2.x * i40, b2.y * i40, b2.z * i40, b2.w * i40));
    store_mean4(5504 + (size_t)dia, c,
        make_float4((b0.x + b1.x + b2.x) * i120, (b0.y + b1.y + b2.y) * i120,
                    (b0.z + b1.z + b2.z) * i120, (b0.w + b1.w + b2.w) * i120));
}

// ---------------------------------------------------------------------------
// Combine + assemble
// ---------------------------------------------------------------------------
__global__ void combine_kernel(float* __restrict__ out)
{
    int idx = blockIdx.x * blockDim.x + threadIdx.x;
    if (idx >= N_NODE * 128) return;
    int c    = (idx & 127) * 4;
    int node = idx >> 7;
    int dia  = node / ROWS_PER_DIA;
    int r    = node - dia * ROWS_PER_DIA;
    int m    = r / L_DIA;
    int t    = r - m * L_DIA;
    int u    = dia * L_DIA + t;

    float4 f  = *(const float4*)(g_feats + (size_t)node * NHID + c);
    float4 x1 = *(const float4*)(g_x1 + (size_t)node * NHID + c);
    float4 ga = *(const float4*)(g_gnn + (size_t)node * NHID + c);
    float4 gt = *(const float4*)(g_gnn + (size_t)(15360 + dia * L_DIA + t) * NHID + c);
    float4 gb = *(const float4*)(g_gnn + (size_t)(20480 + dia * 3 + m) * NHID + c);
    float4 gg = *(const float4*)(g_gnn + (size_t)(20864 + dia) * NHID + c);
    float4 dd = *(const float4*)(g_chBf + (size_t)2048 * NHID + c);

    float4 gnn = make_float4(ga.x + gt.x + gb.x + gg.x + dd.x,
                             ga.y + gt.y + gb.y + gg.y + dd.y,
                             ga.z + gt.z + gb.z + gg.z + dd.z,
                             ga.w + gt.w + gb.w + gg.w + dd.w);

    float* o = out + (size_t)u * OUT_COLS + m * OUT_D2 + c;
    *(float4*)(o)        = f;
    *(float4*)(o + 512)  = x1;
    *(float4*)(o + 1024) = gnn;
}

// ---------------------------------------------------------------------------
extern "C" void kernel_launch(void* const* d_in, const int* in_sizes, int n_in,
                              void* d_out, int out_size)
{
    const float* a      = (const float*)d_in[0];
    const float* v      = (const float*)d_in[1];
    const float* l      = (const float*)d_in[2];
    const float* qmask  = (const float*)d_in[3];
    const float* spk    = (const float*)d_in[4];
    const float* fc1_W  = (const float*)d_in[5];
    const float* fc1_b  = (const float*)d_in[6];
    const float* convW  = (const float*)d_in[7];
    const float* convb  = (const float*)d_in[8];
    float* out = (float*)d_out;

    __nv_bfloat16 *wthi, *wtlo, *fahi, *falo, *x1hi, *x1lo, *mhi, *mlo, *cbhi, *cblo;
    __nv_bfloat16 *chAhi, *chAlo, *chBhi, *chBlo;
    float *x1, *chAf, *chBf, *gnn;
    cudaGetSymbolAddress((void**)&wthi, g_wthi);   cudaGetSymbolAddress((void**)&wtlo, g_wtlo);
    cudaGetSymbolAddress((void**)&fahi, g_fahi);   cudaGetSymbolAddress((void**)&falo, g_falo);
    cudaGetSymbolAddress((void**)&x1,   g_x1);
    cudaGetSymbolAddress((void**)&x1hi, g_x1hi);   cudaGetSymbolAddress((void**)&x1lo, g_x1lo);
    cudaGetSymbolAddress((void**)&mhi,  g_mhi);    cudaGetSymbolAddress((void**)&mlo,  g_mlo);
    cudaGetSymbolAddress((void**)&cbhi, g_cbhi);   cudaGetSymbolAddress((void**)&cblo, g_cblo);
    cudaGetSymbolAddress((void**)&chAhi, g_chAhi); cudaGetSymbolAddress((void**)&chAlo, g_chAlo);
    cudaGetSymbolAddress((void**)&chBhi, g_chBhi); cudaGetSymbolAddress((void**)&chBlo, g_chBlo);
    cudaGetSymbolAddress((void**)&chAf, g_chAf);   cudaGetSymbolAddress((void**)&chBf, g_chBf);
    cudaGetSymbolAddress((void**)&gnn,  g_gnn);

    cudaFuncSetAttribute(gemm_u, cudaFuncAttributeMaxDynamicSharedMemorySize, GEMM_SMEM_BYTES);

    auto mk = [&]() {
        GP p{};
        p.aSwitchY = 1 << 20;
        for (int i = 0; i < 5; i++) {
            p.alpha[i] = 1.f;
            p.yStart[i] = (i == 0) ? 0 : (1 << 20);
        }
        return p;
    };

    // 1. weight prep + chain init
    transpose_split_kernel<<<dim3(16, 16, 5), dim3(32, 8)>>>(fc1_W, convW);
    chain_init_kernel<<<(CHAIN_ROWS * NHID + 255) / 256, 256>>>(convW, convb);

    // 2. chain steps k=2,3,4
    {
        float* srcF[2] = { chAf, chBf };
        __nv_bfloat16* sH[2] = { chAhi, chBhi };
        __nv_bfloat16* sL[2] = { chAlo, chBlo };
        for (int k = 2; k <= 4; k++) {
            int s = k & 1;           // k=2: A->B, k=3: B->A, k=4: A->B
            int d = s ^ 1;
            GP p = mk();
            p.Ahi0 = sH[s]; p.Alo0 = sL[s];
            for (int i = 0; i < 5; i++) {
                p.Bhi[i] = wthi + (size_t)k * MM;
                p.Blo[i] = wtlo + (size_t)k * MM;
                p.yStart[i] = i * 4;
            }
            p.alpha[0] = -1.f / 42.f; p.alpha[1] = 39.f / 42.f;
            p.alpha[2] = 2.f / 42.f;  p.alpha[3] = 1.f; p.alpha[4] = 1.f;
            p.bias[4] = convb + (size_t)(k - 1) * NHID;
            p.Pres = srcF[s];
            p.C = srcF[d]; p.Chi = sH[d]; p.Clo = sL[d];
            gemm_u<<<dim3(4, CHAIN_ROWS / 128), 256, GEMM_SMEM_BYTES>>>(p);
        }
    }
    combo_xpose_kernel<<<dim3(16, 16, 4), dim3(32, 8)>>>();

    // 3. features + x1 GEMM
    build_feats_kernel<<<(N_NODE * 128 + 255) / 256, 256>>>(a, v, l, qmask, spk);
    {
        GP p = mk();
        p.Ahi0 = fahi; p.Alo0 = falo;
        for (int i = 0; i < 5; i++) { p.Bhi[i] = wthi; p.Blo[i] = wtlo; p.bias[i] = fc1_b; }
        p.C = x1; p.Chi = x1hi; p.Clo = x1lo;
        gemm_u<<<dim3(4, N_NODE / 128), 256, GEMM_SMEM_BYTES>>>(p);
    }
    means_kernel<<<D_DIA, 128>>>();

    // 4. mega gnn GEMM: rows 0-119 x1*M0 | 120-159 ft*(MT-M0) | 160-162 fb*(MB-M0) | 163 fg*combo
    {
        GP p = mk();
        p.Ahi0 = x1hi; p.Alo0 = x1lo;
        p.Ahi1 = mhi;  p.Alo1 = mlo;
        p.aSwitchY = 120; p.aRowOfs1 = 15360;
        const int ys[5] = { 0, 120, 160, 163, 1 << 20 };
        for (int i = 0; i < 5; i++) {
            int bi = (i < 4) ? i : 3;
            p.Bhi[i] = cbhi + (size_t)bi * MM;
            p.Blo[i] = cblo + (size_t)bi * MM;
            p.yStart[i] = ys[i];
        }
        p.C = gnn;
        gemm_u<<<dim3(4, GNN_ROWS / 128), 256, GEMM_SMEM_BYTES>>>(p);
    }

    // 5. combine + assemble
    combine_kernel<<<(N_NODE * 128 + 255) / 256, 256>>>(out);
    (void)in_sizes; (void)n_in; (void)out_size;
}

// round 9
// speedup vs baseline: 1.9965x; 1.1420x over previous
#include <cuda_runtime.h>
#include <cuda_bf16.h>
#include <cstdint>

#define D_DIA   128
#define L_DIA   40
#define NHID    512
#define N_UTT   5120
#define N_NODE  15360
#define ROWS_PER_DIA 120
#define OUT_D2  1536
#define OUT_COLS 4608
#define MM      (NHID * NHID)

// GEMM config: BK=64 (128B rows, XOR swizzle), 3 precision passes
#define BM 128
#define BN 128
#define TILE_BYTES (128 * 128)
#define STAGE_BYTES (2 * TILE_BYTES)
#define GEMM_SMEM_BYTES (3 * STAGE_BYTES)   // 96 KB

// outA layout (rows): x1 0..15359 | P1_j 15360+512j | P2_j 17408+512j | bb1 19456 | bb3 19584
#define OUTA_ROWS 19712
#define AFAC_ROWS 4352    // G1_j(2048) G3_j(2048) b1-tile(128@4096) b3-tile(128@4224)
#define MOUT_ROWS 2176    // M_j(2048) + d-tile(128@2048)
#define MEAN_ROWS 5632    // ft(5120) fb(384) fg(128)
#define GNN_ROWS  20992   // node(15360) ft(5120) fb(384) fg(128)

// ---------------------------------------------------------------------------
__device__ float g_feats[N_NODE * NHID];
__device__ __nv_bfloat16 g_fahi[N_NODE * NHID], g_falo[N_NODE * NHID];
__device__ float g_wtf[5 * MM];                       // W^T f32 (w0 fc1, w1..4 conv)
__device__ __nv_bfloat16 g_w0hi[MM], g_w0lo[MM];      // fc1 W^T splits
__device__ float g_outA[OUTA_ROWS * NHID];
__device__ __nv_bfloat16 g_oAhi[OUTA_ROWS * NHID], g_oAlo[OUTA_ROWS * NHID];
__device__ __nv_bfloat16 g_Afhi[AFAC_ROWS * NHID], g_Aflo[AFAC_ROWS * NHID];
__device__ __nv_bfloat16 g_Bfhi[8 * MM], g_Bflo[8 * MM];   // F2_j(4), F4_j(4) B-format
__device__ __nv_bfloat16 g_P2Thi[4 * MM], g_P2Tlo[4 * MM];
__device__ float g_Mout[MOUT_ROWS * NHID];
__device__ float g_means[MEAN_ROWS * NHID];
__device__ __nv_bfloat16 g_mhi[MEAN_ROWS * NHID], g_mlo[MEAN_ROWS * NHID];
__device__ __nv_bfloat16 g_cbhi[4 * MM], g_cblo[4 * MM];
__device__ float g_gnn[GNN_ROWS * NHID];

// ---------------------------------------------------------------------------
__device__ __forceinline__ uint32_t smem_u32(const void* p) {
    uint32_t a;
    asm("{ .reg .u64 t; cvta.to.shared.u64 t, %1; cvt.u32.u64 %0, t; }" : "=r"(a) : "l"(p));
    return a;
}
__device__ __forceinline__ void cp16(uint32_t d, const void* g) {
    asm volatile("cp.async.cg.shared.global [%0], [%1], 16;" :: "r"(d), "l"(g));
}
__device__ __forceinline__ void ldsm4(uint32_t* r, uint32_t addr) {
    asm volatile("ldmatrix.sync.aligned.m8n8.x4.shared.b16 {%0,%1,%2,%3}, [%4];"
        : "=r"(r[0]), "=r"(r[1]), "=r"(r[2]), "=r"(r[3]) : "r"(addr));
}
__device__ __forceinline__ void mma_bf16(float* d, const uint32_t* a, uint32_t b0, uint32_t b1) {
    asm volatile("mma.sync.aligned.m16n8k16.row.col.f32.bf16.bf16.f32 "
        "{%0,%1,%2,%3}, {%4,%5,%6,%7}, {%8,%9}, {%0,%1,%2,%3};"
        : "+f"(d[0]), "+f"(d[1]), "+f"(d[2]), "+f"(d[3])
        : "r"(a[0]), "r"(a[1]), "r"(a[2]), "r"(a[3]), "r"(b0), "r"(b1));
}
__device__ __forceinline__ void split1(float v, __nv_bfloat16& h, __nv_bfloat16& l) {
    h = __float2bfloat16(v);
    l = __float2bfloat16(v - __bfloat162float(h));
}

// ---------------------------------------------------------------------------
// Unified GEMM, 11 y-regions: C = A*B[reg] (+bias[reg]); A ptr/ofs switches at
// aSwitchY. splitK: blockIdx.z = precision pass (3), 8 k-iters, atomicAdd out.
// ---------------------------------------------------------------------------
struct GP {
    const __nv_bfloat16 *Ahi0, *Alo0, *Ahi1, *Alo1;
    int aSwitchY, aRowOfs0, aRowOfs1;
    const __nv_bfloat16 *Bhi[11], *Blo[11];
    const float* bias[11];
    int yStart[11];
    float* C;
    __nv_bfloat16 *Chi, *Clo;
    int splitK;
};

__global__ __launch_bounds__(256, 2)
void gemm_u(GP gp)
{
    extern __shared__ char smem[];
    const uint32_t smem0 = smem_u32(smem);
    const int tid  = threadIdx.x;
    const int lane = tid & 31;
    const int wid  = tid >> 5;
    const int warp_m = wid & 3, warp_n = wid >> 2;
    const int bm = blockIdx.y * BM, bn = blockIdx.x * BN;

    int reg = 0;
    #pragma unroll
    for (int i = 1; i < 11; i++) if ((int)blockIdx.y >= gp.yStart[i]) reg = i;
    const float* bias = gp.bias[reg];

    const __nv_bfloat16 *Ahi, *Alo;
    int arow;
    if ((int)blockIdx.y >= gp.aSwitchY) { Ahi = gp.Ahi1; Alo = gp.Alo1; arow = bm - gp.aRowOfs1; }
    else                                { Ahi = gp.Ahi0; Alo = gp.Alo0; arow = bm - gp.aRowOfs0; }

    float acc[2][8][4];
    #pragma unroll
    for (int i = 0; i < 2; i++)
        #pragma unroll
        for (int j = 0; j < 8; j++)
            #pragma unroll
            for (int q = 0; q < 4; q++) acc[i][j][q] = 0.f;

    const char* AhiP = (const char*)Ahi + (size_t)arow * 1024;
    const char* AloP = (const char*)Alo + (size_t)arow * 1024;
    const char* BhiP = (const char*)gp.Bhi[reg] + (size_t)bn * 1024;
    const char* BloP = (const char*)gp.Blo[reg] + (size_t)bn * 1024;

    const int ktTot = gp.splitK ? 8 : 24;
    const int zpass = gp.splitK ? (int)blockIdx.z : -1;

    auto load_tile = [&](int kt, int s) {
        int p = (zpass >= 0) ? zpass : (kt >> 3);
        const char* Ag = ((p < 2) ? AhiP : AloP) + (kt & 7) * 128;
        const char* Bg = ((p == 1) ? BloP : BhiP) + (kt & 7) * 128;
        uint32_t sa = smem0 + s * STAGE_BYTES;
        #pragma unroll
        for (int i = 0; i < 4; i++) {
            int ci  = i * 256 + tid;
            int row = ci >> 3;
            int c16 = ci & 7;
            uint32_t so = (uint32_t)row * 128 + (uint32_t)((c16 ^ (row & 7)) * 16);
            cp16(sa + so, Ag + (size_t)row * 1024 + c16 * 16);
            cp16(sa + TILE_BYTES + so, Bg + (size_t)row * 1024 + c16 * 16);
        }
        asm volatile("cp.async.commit_group;" ::: "memory");
    };

    const int half = lane >> 4;
    const int lx   = lane & 7;
    const uint32_t aOff = (uint32_t)(warp_m * 32 + (lane & 15)) * 128;
    const uint32_t bOff = (uint32_t)(warp_n * 64 + (lane & 15)) * 128;

    load_tile(0, 0);
    load_tile(1, 1);

    for (int kt = 0; kt < ktTot; kt++) {
        int s = kt % 3;
        asm volatile("cp.async.wait_group 1;" ::: "memory");
        __syncthreads();
        if (kt + 2 < ktTot) load_tile(kt + 2, (kt + 2) % 3);
        else asm volatile("cp.async.commit_group;" ::: "memory");

        const uint32_t sbase = smem0 + (uint32_t)s * STAGE_BYTES;
        #pragma unroll
        for (int k16 = 0; k16 < 4; k16++) {
            const uint32_t co = (uint32_t)(((2 * k16 + half) ^ lx) * 16);
            uint32_t a0[4], a1[4];
            ldsm4(a0, sbase + aOff + co);
            ldsm4(a1, sbase + aOff + 2048 + co);
            #pragma unroll
            for (int q = 0; q < 4; q++) {
                uint32_t b[4];
                ldsm4(b, sbase + TILE_BYTES + bOff + (uint32_t)q * 2048 + co);
                mma_bf16(acc[0][2 * q + 0], a0, b[0], b[2]);
                mma_bf16(acc[0][2 * q + 1], a0, b[1], b[3]);
                mma_bf16(acc[1][2 * q + 0], a1, b[0], b[2]);
                mma_bf16(acc[1][2 * q + 1], a1, b[1], b[3]);
            }
        }
    }

    const int m0 = bm + warp_m * 32;
    const int n0 = bn + warp_n * 64;
    #pragma unroll
    for (int mt = 0; mt < 2; mt++) {
        int r0 = m0 + mt * 16 + (lane >> 2);
        #pragma unroll
        for (int nt = 0; nt < 8; nt++) {
            int col = n0 + nt * 8 + (lane & 3) * 2;
            size_t o0 = (size_t)r0 * NHID + col;
            size_t o1 = (size_t)(r0 + 8) * NHID + col;
            if (gp.splitK) {
                atomicAdd(gp.C + o0,     acc[mt][nt][0]);
                atomicAdd(gp.C + o0 + 1, acc[mt][nt][1]);
                atomicAdd(gp.C + o1,     acc[mt][nt][2]);
                atomicAdd(gp.C + o1 + 1, acc[mt][nt][3]);
            } else {
                float2 v0 = make_float2(acc[mt][nt][0], acc[mt][nt][1]);
                float2 v1 = make_float2(acc[mt][nt][2], acc[mt][nt][3]);
                if (bias) {
                    float bx = bias[col], by = bias[col + 1];
                    v0.x += bx; v0.y += by; v1.x += bx; v1.y += by;
                }
                *(float2*)(gp.C + o0) = v0;
                *(float2*)(gp.C + o1) = v1;
                if (gp.Chi) {
                    __nv_bfloat16 h, l;
                    split1(v0.x, h, l); gp.Chi[o0] = h;     gp.Clo[o0] = l;
                    split1(v0.y, h, l); gp.Chi[o0 + 1] = h; gp.Clo[o0 + 1] = l;
                    split1(v1.x, h, l); gp.Chi[o1] = h;     gp.Clo[o1] = l;
                    split1(v1.y, h, l); gp.Chi[o1 + 1] = h; gp.Clo[o1 + 1] = l;
                }
            }
        }
    }
}

// ---------------------------------------------------------------------------
// Weight transpose: wtf[w][n][k] = W[w][k][n] (f32); splits only for w=0.
// ---------------------------------------------------------------------------
__global__ void transpose_split_kernel(const float* __restrict__ fc1W,
                                       const float* __restrict__ convW)
{
    __shared__ float tile[32][33];
    int w = blockIdx.z;
    const float* W = (w == 0) ? fc1W : convW + (size_t)(w - 1) * MM;
    int n0 = blockIdx.x * 32, k0 = blockIdx.y * 32;
    #pragma unroll
    for (int i = 0; i < 32; i += 8)
        tile[threadIdx.y + i][threadIdx.x] = W[(size_t)(k0 + threadIdx.y + i) * NHID + n0 + threadIdx.x];
    __syncthreads();
    #pragma unroll
    for (int i = 0; i < 32; i += 8) {
        float v = tile[threadIdx.x][threadIdx.y + i];
        size_t o = (size_t)w * MM + (size_t)(n0 + threadIdx.y + i) * NHID + k0 + threadIdx.x;
        g_wtf[o] = v;
        if (w == 0) split1(v, g_w0hi[o], g_w0lo[o]);
    }
}

// ---------------------------------------------------------------------------
// Prep: A-factors G1_j=I+λjC1, G3_j=I+λjC3 (+b1/b3 rows, zero pad), B-factors
// F2_j=(I+λjC2)^T, F4_j=(I+λjC4)^T, and zero Mout.
// ---------------------------------------------------------------------------
#define A_ELEMS (AFAC_ROWS * NHID)
#define B_ELEMS (8 * MM)
#define PREP_TOTAL (A_ELEMS + B_ELEMS + MOUT_ROWS * NHID)

__global__ void prep_kernel(const float* __restrict__ convW,
                            const float* __restrict__ convb)
{
    int idx = blockIdx.x * blockDim.x + threadIdx.x;
    if (idx >= PREP_TOTAL) return;
    const float L[4] = { -1.f / 42.f, 39.f / 42.f, 2.f / 42.f, 1.f };
    if (idx < A_ELEMS) {
        int r = idx >> 9, c = idx & 511;
        float v = 0.f;
        if (r < 2048) {
            int rr = r & 511;
            v = L[r >> 9] * convW[(size_t)rr * NHID + c] + ((rr == c) ? 1.f : 0.f);
        } else if (r < 4096) {
            int r2 = r - 2048, rr = r2 & 511;
            v = L[r2 >> 9] * convW[2 * (size_t)MM + (size_t)rr * NHID + c] + ((rr == c) ? 1.f : 0.f);
        } else if (r == 4096) v = convb[c];
        else if (r == 4224) v = convb[2 * NHID + c];
        split1(v, g_Afhi[idx], g_Aflo[idx]);
    } else if (idx < A_ELEMS + B_ELEMS) {
        int i = idx - A_ELEMS;
        int g = i >> 18;
        int nk = i & (MM - 1);
        int n = nk >> 9, k = nk & 511;
        int j = g & 3;
        int w = (g < 4) ? 2 : 4;          // C2^T or C4^T in wtf
        float v = L[j] * g_wtf[(size_t)w * MM + nk] + ((n == k) ? 1.f : 0.f);
        split1(v, g_Bfhi[i], g_Bflo[i]);
    } else {
        g_Mout[idx - A_ELEMS - B_ELEMS] = 0.f;
    }
}

// ---------------------------------------------------------------------------
// Build node features + splits
// ---------------------------------------------------------------------------
__global__ void build_feats_kernel(const float* __restrict__ a,
                                   const float* __restrict__ v,
                                   const float* __restrict__ l,
                                   const float* __restrict__ qmask,
                                   const float* __restrict__ spk)
{
    int idx = blockIdx.x * blockDim.x + threadIdx.x;
    if (idx >= N_NODE * 128) return;
    int c    = (idx & 127) * 4;
    int node = idx >> 7;
    int dia  = node / ROWS_PER_DIA;
    int r    = node - dia * ROWS_PER_DIA;
    int m    = r / L_DIA;
    int t    = r - m * L_DIA;
    int u    = dia * L_DIA + t;

    float4 val;
    if (m == 0) {
        float q0 = qmask[(t * D_DIA + dia) * 2 + 0];
        float q1 = qmask[(t * D_DIA + dia) * 2 + 1];
        int s = (q1 > q0) ? 1 : 0;
        float4 lv = *(const float4*)(l + (size_t)u * NHID + c);
        float4 sv = *(const float4*)(spk + (size_t)s * NHID + c);
        val = make_float4(lv.x + sv.x, lv.y + sv.y, lv.z + sv.z, lv.w + sv.w);
    } else if (m == 1) {
        val = *(const float4*)(a + (size_t)u * NHID + c);
    } else {
        val = *(const float4*)(v + (size_t)u * NHID + c);
    }
    size_t o = (size_t)node * NHID + c;
    *(float4*)(g_feats + o) = val;
    split1(val.x, g_fahi[o],     g_falo[o]);
    split1(val.y, g_fahi[o + 1], g_falo[o + 1]);
    split1(val.z, g_fahi[o + 2], g_falo[o + 2]);
    split1(val.w, g_fahi[o + 3], g_falo[o + 3]);
}

// ---------------------------------------------------------------------------
// Misc (one launch): [0,1024) transpose P2_j -> B-splits; [1024,1152) means;
// [1152] dA row = bb1 + b2 -> splits into outA row 19456.
// ---------------------------------------------------------------------------
__device__ __forceinline__ void store_mean2(size_t row, int c, float x, float y)
{
    size_t o = row * NHID + c;
    g_means[o] = x; g_means[o + 1] = y;
    split1(x, g_mhi[o],     g_mlo[o]);
    split1(y, g_mhi[o + 1], g_mlo[o + 1]);
}

__global__ void misc_kernel(const float* __restrict__ convb)
{
    __shared__ float tile[32][33];
    int b = blockIdx.x, tid = threadIdx.x;
    if (b < 1024) {
        int z = b >> 8, t = b & 255;
        int r0 = (t >> 4) * 32, c0 = (t & 15) * 32;
        int tx = tid & 31, ty = tid >> 5;
        #pragma unroll
        for (int i = 0; i < 32; i += 8)
            tile[ty + i][tx] = g_outA[(size_t)(17408 + z * 512 + r0 + ty + i) * NHID + c0 + tx];
        __syncthreads();
        #pragma unroll
        for (int i = 0; i < 32; i += 8) {
            size_t o = (size_t)z * MM + (size_t)(c0 + ty + i) * NHID + r0 + tx;
            split1(tile[tx][ty + i], g_P2Thi[o], g_P2Tlo[o]);
        }
    } else if (b < 1152) {
        int dia = b - 1024;
        int c = tid * 2;
        const float* xb = g_outA + (size_t)dia * ROWS_PER_DIA * NHID;
        float s0x = 0, s0y = 0, s1x = 0, s1y = 0, s2x = 0, s2y = 0;
        for (int t = 0; t < L_DIA; t++) {
            float2 v0 = *(const float2*)(xb + (size_t)t * NHID + c);
            float2 v1 = *(const float2*)(xb + (size_t)(L_DIA + t) * NHID + c);
            float2 v2 = *(const float2*)(xb + (size_t)(2 * L_DIA + t) * NHID + c);
            s0x += v0.x; s0y += v0.y;
            s1x += v1.x; s1y += v1.y;
            s2x += v2.x; s2y += v2.y;
            const float i3 = 1.f / 3.f;
            store_mean2((size_t)dia * L_DIA + t, c,
                        (v0.x + v1.x + v2.x) * i3, (v0.y + v1.y + v2.y) * i3);
        }
        const float i40 = 1.f / 40.f, i120 = 1.f / 120.f;
        store_mean2(5120 + (size_t)dia * 3 + 0, c, s0x * i40, s0y * i40);
        store_mean2(5120 + (size_t)dia * 3 + 1, c, s1x * i40, s1y * i40);
        store_mean2(5120 + (size_t)dia * 3 + 2, c, s2x * i40, s2y * i40);
        store_mean2(5504 + (size_t)dia, c, (s0x + s1x + s2x) * i120, (s0y + s1y + s2y) * i120);
    } else {
        int c = tid * 2;
        size_t o = (size_t)19456 * NHID + c;
        float2 v  = *(const float2*)(g_outA + o);
        float2 b2 = *(const float2*)(convb + NHID + c);
        split1(v.x + b2.x, g_oAhi[o],     g_oAlo[o]);
        split1(v.y + b2.y, g_oAhi[o + 1], g_oAlo[o + 1]);
    }
}

// ---------------------------------------------------------------------------
// Combos of M_j (from g_Mout) -> B-format splits:
// z0 M0^T; z1 (MT-M0)^T; z2 (MB-M0)^T; z3 (M0-MB-MT+MG)^T
// ---------------------------------------------------------------------------
__global__ void combo_xpose_kernel()
{
    __shared__ float tile[32][33];
    const float CF[4][4] = { {1,0,0,0}, {-1,0,1,0}, {-1,1,0,0}, {1,-1,-1,1} };
    int z = blockIdx.z;
    int c0 = blockIdx.x * 32, r0 = blockIdx.y * 32;
    #pragma unroll
    for (int i = 0; i < 32; i += 8) {
        size_t rc = (size_t)(r0 + threadIdx.y + i) * NHID + c0 + threadIdx.x;
        float v = 0.f;
        #pragma unroll
        for (int j = 0; j < 4; j++)
            if (CF[z][j] != 0.f) v += CF[z][j] * g_Mout[(size_t)j * 512 * NHID + rc];
        tile[threadIdx.y + i][threadIdx.x] = v;
    }
    __syncthreads();
    #pragma unroll
    for (int i = 0; i < 32; i += 8) {
        size_t o = (size_t)z * MM + (size_t)(c0 + threadIdx.y + i) * NHID + r0 + threadIdx.x;
        split1(tile[threadIdx.x][threadIdx.y + i], g_cbhi[o], g_cblo[o]);
    }
}

// ---------------------------------------------------------------------------
// Combine + assemble. dd = d0 + bb3 + b4.
// ---------------------------------------------------------------------------
__global__ void combine_kernel(const float* __restrict__ convb, float* __restrict__ out)
{
    int idx = blockIdx.x * blockDim.x + threadIdx.x;
    if (idx >= N_NODE * 128) return;
    int c    = (idx & 127) * 4;
    int node = idx >> 7;
    int dia  = node / ROWS_PER_DIA;
    int r    = node - dia * ROWS_PER_DIA;
    int m    = r / L_DIA;
    int t    = r - m * L_DIA;
    int u    = dia * L_DIA + t;

    float4 f  = *(const float4*)(g_feats + (size_t)node * NHID + c);
    float4 x1 = *(const float4*)(g_outA + (size_t)node * NHID + c);
    float4 ga = *(const float4*)(g_gnn + (size_t)node * NHID + c);
    float4 gt = *(const float4*)(g_gnn + (size_t)(15360 + dia * L_DIA + t) * NHID + c);
    float4 gb = *(const float4*)(g_gnn + (size_t)(20480 + dia * 3 + m) * NHID + c);
    float4 gg = *(const float4*)(g_gnn + (size_t)(20864 + dia) * NHID + c);
    float4 d0 = *(const float4*)(g_Mout + (size_t)2048 * NHID + c);
    float4 b3r = *(const float4*)(g_outA + (size_t)19584 * NHID + c);
    float4 b4 = *(const float4*)(convb + 3 * NHID + c);

    float4 gnn = make_float4(
        ga.x + gt.x + gb.x + gg.x + d0.x + b3r.x + b4.x,
        ga.y + gt.y + gb.y + gg.y + d0.y + b3r.y + b4.y,
        ga.z + gt.z + gb.z + gg.z + d0.z + b3r.z + b4.z,
        ga.w + gt.w + gb.w + gg.w + d0.w + b3r.w + b4.w);

    float* o = out + (size_t)u * OUT_COLS + m * OUT_D2 + c;
    *(float4*)(o)        = f;
    *(float4*)(o + 512)  = x1;
    *(float4*)(o + 1024) = gnn;
}

// ---------------------------------------------------------------------------
extern "C" void kernel_launch(void* const* d_in, const int* in_sizes, int n_in,
                              void* d_out, int out_size)
{
    const float* a      = (const float*)d_in[0];
    const float* v      = (const float*)d_in[1];
    const float* l      = (const float*)d_in[2];
    const float* qmask  = (const float*)d_in[3];
    const float* spk    = (const float*)d_in[4];
    const float* fc1_W  = (const float*)d_in[5];
    const float* fc1_b  = (const float*)d_in[6];
    const float* convW  = (const float*)d_in[7];
    const float* convb  = (const float*)d_in[8];
    float* out = (float*)d_out;

    __nv_bfloat16 *w0hi, *w0lo, *fahi, *falo, *oAhi, *oAlo, *Afhi, *Aflo;
    __nv_bfloat16 *Bfhi, *Bflo, *P2Thi, *P2Tlo, *mhi, *mlo, *cbhi, *cblo;
    float *outA, *Mout, *gnn;
    cudaGetSymbolAddress((void**)&w0hi, g_w0hi);   cudaGetSymbolAddress((void**)&w0lo, g_w0lo);
    cudaGetSymbolAddress((void**)&fahi, g_fahi);   cudaGetSymbolAddress((void**)&falo, g_falo);
    cudaGetSymbolAddress((void**)&oAhi, g_oAhi);   cudaGetSymbolAddress((void**)&oAlo, g_oAlo);
    cudaGetSymbolAddress((void**)&Afhi, g_Afhi);   cudaGetSymbolAddress((void**)&Aflo, g_Aflo);
    cudaGetSymbolAddress((void**)&Bfhi, g_Bfhi);   cudaGetSymbolAddress((void**)&Bflo, g_Bflo);
    cudaGetSymbolAddress((void**)&P2Thi, g_P2Thi); cudaGetSymbolAddress((void**)&P2Tlo, g_P2Tlo);
    cudaGetSymbolAddress((void**)&mhi, g_mhi);     cudaGetSymbolAddress((void**)&mlo, g_mlo);
    cudaGetSymbolAddress((void**)&cbhi, g_cbhi);   cudaGetSymbolAddress((void**)&cblo, g_cblo);
    cudaGetSymbolAddress((void**)&outA, g_outA);
    cudaGetSymbolAddress((void**)&Mout, g_Mout);
    cudaGetSymbolAddress((void**)&gnn, g_gnn);

    cudaFuncSetAttribute(gemm_u, cudaFuncAttributeMaxDynamicSharedMemorySize, GEMM_SMEM_BYTES);

    const int BIG = 1 << 20;

    // 1. transpose weights (f32 all, splits for fc1)
    transpose_split_kernel<<<dim3(16, 16, 5), dim3(32, 8)>>>(fc1_W, convW);
    // 2. prep factors + zero Mout
    prep_kernel<<<(PREP_TOTAL + 255) / 256, 256>>>(convW, convb);
    // 3. features
    build_feats_kernel<<<(N_NODE * 128 + 255) / 256, 256>>>(a, v, l, qmask, spk);

    // 4. MEGA-A: x1 + pairwise products + bias rows  (grid 4 x 154)
    {
        GP p{};
        p.Ahi0 = fahi; p.Alo0 = falo;
        p.Ahi1 = Afhi; p.Alo1 = Aflo;
        p.aSwitchY = 120; p.aRowOfs0 = 0; p.aRowOfs1 = 15360;
        const int ys[11]   = { 0, 120, 124, 128, 132, 136, 140, 144, 148, 152, 153 };
        const int bofs[11] = { -1, 0, 1, 2, 3, 4, 5, 6, 7, 3, 7 };
        for (int i = 0; i < 11; i++) {
            p.yStart[i] = ys[i];
            if (i == 0) { p.Bhi[i] = w0hi; p.Blo[i] = w0lo; }
            else        { p.Bhi[i] = Bfhi + (size_t)bofs[i] * MM; p.Blo[i] = Bflo + (size_t)bofs[i] * MM; }
        }
        p.bias[0] = fc1_b;
        p.C = outA; p.Chi = oAhi; p.Clo = oAlo;
        p.splitK = 0;
        gemm_u<<<dim3(4, OUTA_ROWS / 128), 256, GEMM_SMEM_BYTES>>>(p);
    }

    // 5. misc: P2 transpose-splits + means + dA row
    misc_kernel<<<1153, 256>>>(convb);

    // 6. step B: M_j = P1_j * P2_j and d0 = dA * P2_3  (split-K, grid 4x17x3)
    {
        GP p{};
        p.Ahi0 = oAhi; p.Alo0 = oAlo;
        p.Ahi1 = oAhi; p.Alo1 = oAlo;
        p.aSwitchY = 16; p.aRowOfs0 = -15360; p.aRowOfs1 = -17408;
        const int ys[11]   = { 0, 4, 8, 12, 16, BIG, BIG, BIG, BIG, BIG, BIG };
        const int bofs[11] = { 0, 1, 2, 3, 3, 3, 3, 3, 3, 3, 3 };
        for (int i = 0; i < 11; i++) {
            p.yStart[i] = ys[i];
            p.Bhi[i] = P2Thi + (size_t)bofs[i] * MM;
            p.Blo[i] = P2Tlo + (size_t)bofs[i] * MM;
        }
        p.C = Mout; p.Chi = nullptr; p.Clo = nullptr;
        p.splitK = 1;
        gemm_u<<<dim3(4, MOUT_ROWS / 128, 3), 256, GEMM_SMEM_BYTES>>>(p);
    }

    // 7. combos -> B-format
    combo_xpose_kernel<<<dim3(16, 16, 4), dim3(32, 8)>>>();

    // 8. MEGA-gnn  (grid 4 x 164)
    {
        GP p{};
        p.Ahi0 = oAhi; p.Alo0 = oAlo;
        p.Ahi1 = mhi;  p.Alo1 = mlo;
        p.aSwitchY = 120; p.aRowOfs0 = 0; p.aRowOfs1 = 15360;
        const int ys[11] = { 0, 120, 160, 163, BIG, BIG, BIG, BIG, BIG, BIG, BIG };
        for (int i = 0; i < 11; i++) {
            p.yStart[i] = ys[i];
            int bi = (i < 4) ? i : 3;
            p.Bhi[i] = cbhi + (size_t)bi * MM;
            p.Blo[i] = cblo + (size_t)bi * MM;
        }
        p.C = gnn; p.Chi = nullptr; p.Clo = nullptr;
        p.splitK = 0;
        gemm_u<<<dim3(4, GNN_ROWS / 128), 256, GEMM_SMEM_BYTES>>>(p);
    }

    // 9. combine + assemble
    combine_kernel<<<(N_NODE * 128 + 255) / 256, 256>>>(convb, out);
    (void)in_sizes; (void)n_in; (void)out_size;
}

// round 11
// speedup vs baseline: 2.3006x; 1.1524x over previous
#include <cuda_runtime.h>
#include <cuda_fp16.h>
#include <cstdint>

#define D_DIA   128
#define L_DIA   40
#define NHID    512
#define N_UTT   5120
#define N_NODE  15360
#define ROWS_PER_DIA 120
#define OUT_D2  1536
#define OUT_COLS 4608
#define MM      (NHID * NHID)

// GEMM config: BK=64 (128B rows, XOR swizzle), fp16, 2 or 3 precision passes
#define BM 128
#define BN 128
#define TILE_BYTES (128 * 128)
#define STAGE_BYTES (2 * TILE_BYTES)
#define GEMM_SMEM_BYTES (3 * STAGE_BYTES)   // 96 KB

// outA layout (rows): x1 0..15359 | P1_j 15360+512j | P2_j 17408+512j | bb1 19456 | bb3 19584
#define OUTA_ROWS 19712
#define AFAC_ROWS 4352    // G1_j(2048) G3_j(2048) b1-tile(128@4096) b3-tile(128@4224)
#define MOUT_ROWS 2176    // M_j(2048) + d-tile(128@2048)
#define MEAN_ROWS 5632    // ft(5120) fb(384) fg(128)
#define GNN_ROWS  20992   // node(15360) ft(5120) fb(384) fg(128)

// ---------------------------------------------------------------------------
__device__ float g_feats[N_NODE * NHID];
__device__ __half g_fahi[N_NODE * NHID], g_falo[N_NODE * NHID];
__device__ float g_wtf[5 * MM];                 // W^T f32 (w0 fc1, w1..4 conv)
__device__ __half g_w0hi[MM], g_w0lo[MM];       // fc1 W^T splits
__device__ float g_outA[OUTA_ROWS * NHID];
__device__ __half g_oAhi[OUTA_ROWS * NHID], g_oAlo[OUTA_ROWS * NHID];
__device__ __half g_Afhi[AFAC_ROWS * NHID], g_Aflo[AFAC_ROWS * NHID];
__device__ __half g_Bfhi[8 * MM], g_Bflo[8 * MM];   // F2_j(4), F4_j(4) B-format
__device__ __half g_P2Thi[4 * MM], g_P2Tlo[4 * MM];
__device__ float g_Mout[MOUT_ROWS * NHID];
__device__ float g_means[MEAN_ROWS * NHID];
__device__ __half g_mhi[MEAN_ROWS * NHID], g_mlo[MEAN_ROWS * NHID];
__device__ __half g_cbhi[4 * MM], g_cblo[4 * MM];
__device__ float g_gnn[GNN_ROWS * NHID];

// ---------------------------------------------------------------------------
__device__ __forceinline__ uint32_t smem_u32(const void* p) {
    uint32_t a;
    asm("{ .reg .u64 t; cvta.to.shared.u64 t, %1; cvt.u32.u64 %0, t; }" : "=r"(a) : "l"(p));
    return a;
}
__device__ __forceinline__ void cp16(uint32_t d, const void* g) {
    asm volatile("cp.async.cg.shared.global [%0], [%1], 16;" :: "r"(d), "l"(g));
}
__device__ __forceinline__ void ldsm4(uint32_t* r, uint32_t addr) {
    asm volatile("ldmatrix.sync.aligned.m8n8.x4.shared.b16 {%0,%1,%2,%3}, [%4];"
        : "=r"(r[0]), "=r"(r[1]), "=r"(r[2]), "=r"(r[3]) : "r"(addr));
}
__device__ __forceinline__ void mma_f16(float* d, const uint32_t* a, uint32_t b0, uint32_t b1) {
    asm volatile("mma.sync.aligned.m16n8k16.row.col.f32.f16.f16.f32 "
        "{%0,%1,%2,%3}, {%4,%5,%6,%7}, {%8,%9}, {%0,%1,%2,%3};"
        : "+f"(d[0]), "+f"(d[1]), "+f"(d[2]), "+f"(d[3])
        : "r"(a[0]), "r"(a[1]), "r"(a[2]), "r"(a[3]), "r"(b0), "r"(b1));
}
__device__ __forceinline__ void split1(float v, __half& h, __half& l) {
    h = __float2half_rn(v);
    l = __float2half_rn(v - __half2float(h));
}

// ---------------------------------------------------------------------------
// Unified GEMM, 11 y-regions: C = A*B[reg] (+bias[reg]); A ptr/ofs switches at
// aSwitchY. kt16mask bit reg => 2-pass (16 iters) else 3-pass (24).
// splitK: blockIdx.z = precision pass (3), 8 k-iters, atomicAdd out.
// ---------------------------------------------------------------------------
struct GP {
    const __half *Ahi0, *Alo0, *Ahi1, *Alo1;
    int aSwitchY, aRowOfs0, aRowOfs1;
    const __half *Bhi[11], *Blo[11];
    const float* bias[11];
    int yStart[11];
    float* C;
    __half *Chi, *Clo;
    int splitK;
    int kt16mask;
};

__global__ __launch_bounds__(256, 2)
void gemm_u(GP gp)
{
    extern __shared__ char smem[];
    const uint32_t smem0 = smem_u32(smem);
    const int tid  = threadIdx.x;
    const int lane = tid & 31;
    const int wid  = tid >> 5;
    const int warp_m = wid & 3, warp_n = wid >> 2;
    const int bm = blockIdx.y * BM, bn = blockIdx.x * BN;

    int reg = 0;
    #pragma unroll
    for (int i = 1; i < 11; i++) if ((int)blockIdx.y >= gp.yStart[i]) reg = i;
    const float* bias = gp.bias[reg];

    const __half *Ahi, *Alo;
    int arow;
    if ((int)blockIdx.y >= gp.aSwitchY) { Ahi = gp.Ahi1; Alo = gp.Alo1; arow = bm - gp.aRowOfs1; }
    else                                { Ahi = gp.Ahi0; Alo = gp.Alo0; arow = bm - gp.aRowOfs0; }

    float acc[2][8][4];
    #pragma unroll
    for (int i = 0; i < 2; i++)
        #pragma unroll
        for (int j = 0; j < 8; j++)
            #pragma unroll
            for (int q = 0; q < 4; q++) acc[i][j][q] = 0.f;

    const char* AhiP = (const char*)Ahi + (size_t)arow * 1024;
    const char* AloP = (const char*)Alo + (size_t)arow * 1024;
    const char* BhiP = (const char*)gp.Bhi[reg] + (size_t)bn * 1024;
    const char* BloP = (const char*)gp.Blo[reg] + (size_t)bn * 1024;

    const bool tp = (!gp.splitK) && (((gp.kt16mask >> reg) & 1) != 0);   // 2-pass mode
    const int ktTot = gp.splitK ? 8 : (tp ? 16 : 24);
    const int zpass = gp.splitK ? (int)blockIdx.z : -1;

    auto load_tile = [&](int kt, int s) {
        int p = (zpass >= 0) ? zpass : (kt >> 3);
        bool aHi = tp ? (p == 0) : (p < 2);
        bool bLo = (!tp) && (p == 1);
        const char* Ag = (aHi ? AhiP : AloP) + (kt & 7) * 128;
        const char* Bg = (bLo ? BloP : BhiP) + (kt & 7) * 128;
        uint32_t sa = smem0 + s * STAGE_BYTES;
        #pragma unroll
        for (int i = 0; i < 4; i++) {
            int ci  = i * 256 + tid;
            int row = ci >> 3;
            int c16 = ci & 7;
            uint32_t so = (uint32_t)row * 128 + (uint32_t)((c16 ^ (row & 7)) * 16);
            cp16(sa + so, Ag + (size_t)row * 1024 + c16 * 16);
            cp16(sa + TILE_BYTES + so, Bg + (size_t)row * 1024 + c16 * 16);
        }
        asm volatile("cp.async.commit_group;" ::: "memory");
    };

    const int half_ = lane >> 4;
    const int lx    = lane & 7;
    const uint32_t aOff = (uint32_t)(warp_m * 32 + (lane & 15)) * 128;
    const uint32_t bOff = (uint32_t)(warp_n * 64 + (lane & 15)) * 128;

    load_tile(0, 0);
    load_tile(1, 1);

    for (int kt = 0; kt < ktTot; kt++) {
        int s = kt % 3;
        asm volatile("cp.async.wait_group 1;" ::: "memory");
        __syncthreads();
        if (kt + 2 < ktTot) load_tile(kt + 2, (kt + 2) % 3);
        else asm volatile("cp.async.commit_group;" ::: "memory");

        const uint32_t sbase = smem0 + (uint32_t)s * STAGE_BYTES;
        #pragma unroll
        for (int k16 = 0; k16 < 4; k16++) {
            const uint32_t co = (uint32_t)(((2 * k16 + half_) ^ lx) * 16);
            uint32_t a0[4], a1[4];
            ldsm4(a0, sbase + aOff + co);
            ldsm4(a1, sbase + aOff + 2048 + co);
            #pragma unroll
            for (int q = 0; q < 4; q++) {
                uint32_t b[4];
                ldsm4(b, sbase + TILE_BYTES + bOff + (uint32_t)q * 2048 + co);
                mma_f16(acc[0][2 * q + 0], a0, b[0], b[2]);
                mma_f16(acc[0][2 * q + 1], a0, b[1], b[3]);
                mma_f16(acc[1][2 * q + 0], a1, b[0], b[2]);
                mma_f16(acc[1][2 * q + 1], a1, b[1], b[3]);
            }
        }
    }

    const int m0 = bm + warp_m * 32;
    const int n0 = bn + warp_n * 64;
    #pragma unroll
    for (int mt = 0; mt < 2; mt++) {
        int r0 = m0 + mt * 16 + (lane >> 2);
        #pragma unroll
        for (int nt = 0; nt < 8; nt++) {
            int col = n0 + nt * 8 + (lane & 3) * 2;
            size_t o0 = (size_t)r0 * NHID + col;
            size_t o1 = (size_t)(r0 + 8) * NHID + col;
            if (gp.splitK) {
                atomicAdd(gp.C + o0,     acc[mt][nt][0]);
                atomicAdd(gp.C + o0 + 1, acc[mt][nt][1]);
                atomicAdd(gp.C + o1,     acc[mt][nt][2]);
                atomicAdd(gp.C + o1 + 1, acc[mt][nt][3]);
            } else {
                float2 v0 = make_float2(acc[mt][nt][0], acc[mt][nt][1]);
                float2 v1 = make_float2(acc[mt][nt][2], acc[mt][nt][3]);
                if (bias) {
                    float bx = bias[col], by = bias[col + 1];
                    v0.x += bx; v0.y += by; v1.x += bx; v1.y += by;
                }
                *(float2*)(gp.C + o0) = v0;
                *(float2*)(gp.C + o1) = v1;
                if (gp.Chi) {
                    __half h, l;
                    split1(v0.x, h, l); gp.Chi[o0] = h;     gp.Clo[o0] = l;
                    split1(v0.y, h, l); gp.Chi[o0 + 1] = h; gp.Clo[o0 + 1] = l;
                    split1(v1.x, h, l); gp.Chi[o1] = h;     gp.Clo[o1] = l;
                    split1(v1.y, h, l); gp.Chi[o1 + 1] = h; gp.Clo[o1 + 1] = l;
                }
            }
        }
    }
}

// ---------------------------------------------------------------------------
// Weight transpose: wtf[w][n][k] = W[w][k][n] (f32); splits only for w=0.
// ---------------------------------------------------------------------------
__global__ void transpose_split_kernel(const float* __restrict__ fc1W,
                                       const float* __restrict__ convW)
{
    __shared__ float tile[32][33];
    int w = blockIdx.z;
    const float* W = (w == 0) ? fc1W : convW + (size_t)(w - 1) * MM;
    int n0 = blockIdx.x * 32, k0 = blockIdx.y * 32;
    #pragma unroll
    for (int i = 0; i < 32; i += 8)
        tile[threadIdx.y + i][threadIdx.x] = W[(size_t)(k0 + threadIdx.y + i) * NHID + n0 + threadIdx.x];
    __syncthreads();
    #pragma unroll
    for (int i = 0; i < 32; i += 8) {
        float v = tile[threadIdx.x][threadIdx.y + i];
        size_t o = (size_t)w * MM + (size_t)(n0 + threadIdx.y + i) * NHID + k0 + threadIdx.x;
        g_wtf[o] = v;
        if (w == 0) split1(v, g_w0hi[o], g_w0lo[o]);
    }
}

// ---------------------------------------------------------------------------
// Prep: A-factors G1_j=I+λjC1, G3_j=I+λjC3 (+b1/b3 rows, zero pad), B-factors
// F2_j=(I+λjC2)^T, F4_j=(I+λjC4)^T, and zero Mout.
// ---------------------------------------------------------------------------
#define A_ELEMS (AFAC_ROWS * NHID)
#define B_ELEMS (8 * MM)
#define PREP_TOTAL (A_ELEMS + B_ELEMS + MOUT_ROWS * NHID)

__global__ void prep_kernel(const float* __restrict__ convW,
                            const float* __restrict__ convb)
{
    int idx = blockIdx.x * blockDim.x + threadIdx.x;
    if (idx >= PREP_TOTAL) return;
    const float L[4] = { -1.f / 42.f, 39.f / 42.f, 2.f / 42.f, 1.f };
    if (idx < A_ELEMS) {
        int r = idx >> 9, c = idx & 511;
        float v = 0.f;
        if (r < 2048) {
            int rr = r & 511;
            v = L[r >> 9] * convW[(size_t)rr * NHID + c] + ((rr == c) ? 1.f : 0.f);
        } else if (r < 4096) {
            int r2 = r - 2048, rr = r2 & 511;
            v = L[r2 >> 9] * convW[2 * (size_t)MM + (size_t)rr * NHID + c] + ((rr == c) ? 1.f : 0.f);
        } else if (r == 4096) v = convb[c];
        else if (r == 4224) v = convb[2 * NHID + c];
        split1(v, g_Afhi[idx], g_Aflo[idx]);
    } else if (idx < A_ELEMS + B_ELEMS) {
        int i = idx - A_ELEMS;
        int g = i >> 18;
        int nk = i & (MM - 1);
        int n = nk >> 9, k = nk & 511;
        int j = g & 3;
        int w = (g < 4) ? 2 : 4;          // C2^T or C4^T in wtf
        float v = L[j] * g_wtf[(size_t)w * MM + nk] + ((n == k) ? 1.f : 0.f);
        split1(v, g_Bfhi[i], g_Bflo[i]);
    } else {
        g_Mout[idx - A_ELEMS - B_ELEMS] = 0.f;
    }
}

// ---------------------------------------------------------------------------
// Build node features + splits
// ---------------------------------------------------------------------------
__global__ void build_feats_kernel(const float* __restrict__ a,
                                   const float* __restrict__ v,
                                   const float* __restrict__ l,
                                   const float* __restrict__ qmask,
                                   const float* __restrict__ spk)
{
    int idx = blockIdx.x * blockDim.x + threadIdx.x;
    if (idx >= N_NODE * 128) return;
    int c    = (idx & 127) * 4;
    int node = idx >> 7;
    int dia  = node / ROWS_PER_DIA;
    int r    = node - dia * ROWS_PER_DIA;
    int m    = r / L_DIA;
    int t    = r - m * L_DIA;
    int u    = dia * L_DIA + t;

    float4 val;
    if (m == 0) {
        float q0 = qmask[(t * D_DIA + dia) * 2 + 0];
        float q1 = qmask[(t * D_DIA + dia) * 2 + 1];
        int s = (q1 > q0) ? 1 : 0;
        float4 lv = *(const float4*)(l + (size_t)u * NHID + c);
        float4 sv = *(const float4*)(spk + (size_t)s * NHID + c);
        val = make_float4(lv.x + sv.x, lv.y + sv.y, lv.z + sv.z, lv.w + sv.w);
    } else if (m == 1) {
        val = *(const float4*)(a + (size_t)u * NHID + c);
    } else {
        val = *(const float4*)(v + (size_t)u * NHID + c);
    }
    size_t o = (size_t)node * NHID + c;
    *(float4*)(g_feats + o) = val;
    split1(val.x, g_fahi[o],     g_falo[o]);
    split1(val.y, g_fahi[o + 1], g_falo[o + 1]);
    split1(val.z, g_fahi[o + 2], g_falo[o + 2]);
    split1(val.w, g_fahi[o + 3], g_falo[o + 3]);
}

// ---------------------------------------------------------------------------
// Misc (one launch): [0,1024) transpose P2_j -> B-splits; [1024,1152) means;
// [1152] dA row = bb1 + b2 -> splits into outA row 19456.
// ---------------------------------------------------------------------------
__device__ __forceinline__ void store_mean2(size_t row, int c, float x, float y)
{
    size_t o = row * NHID + c;
    g_means[o] = x; g_means[o + 1] = y;
    split1(x, g_mhi[o],     g_mlo[o]);
    split1(y, g_mhi[o + 1], g_mlo[o + 1]);
}

__global__ void misc_kernel(const float* __restrict__ convb)
{
    __shared__ float tile[32][33];
    int b = blockIdx.x, tid = threadIdx.x;
    if (b < 1024) {
        int z = b >> 8, t = b & 255;
        int r0 = (t >> 4) * 32, c0 = (t & 15) * 32;
        int tx = tid & 31, ty = tid >> 5;
        #pragma unroll
        for (int i = 0; i < 32; i += 8)
            tile[ty + i][tx] = g_outA[(size_t)(17408 + z * 512 + r0 + ty + i) * NHID + c0 + tx];
        __syncthreads();
        #pragma unroll
        for (int i = 0; i < 32; i += 8) {
            size_t o = (size_t)z * MM + (size_t)(c0 + ty + i) * NHID + r0 + tx;
            split1(tile[tx][ty + i], g_P2Thi[o], g_P2Tlo[o]);
        }
    } else if (b < 1152) {
        int dia = b - 1024;
        int c = tid * 2;
        const float* xb = g_outA + (size_t)dia * ROWS_PER_DIA * NHID;
        float s0x = 0, s0y = 0, s1x = 0, s1y = 0, s2x = 0, s2y = 0;
        for (int t = 0; t < L_DIA; t++) {
            float2 v0 = *(const float2*)(xb + (size_t)t * NHID + c);
            float2 v1 = *(const float2*)(xb + (size_t)(L_DIA + t) * NHID + c);
            float2 v2 = *(const float2*)(xb + (size_t)(2 * L_DIA + t) * NHID + c);
            s0x += v0.x; s0y += v0.y;
            s1x += v1.x; s1y += v1.y;
            s2x += v2.x; s2y += v2.y;
            const float i3 = 1.f / 3.f;
            store_mean2((size_t)dia * L_DIA + t, c,
                        (v0.x + v1.x + v2.x) * i3, (v0.y + v1.y + v2.y) * i3);
        }
        const float i40 = 1.f / 40.f, i120 = 1.f / 120.f;
        store_mean2(5120 + (size_t)dia * 3 + 0, c, s0x * i40, s0y * i40);
        store_mean2(5120 + (size_t)dia * 3 + 1, c, s1x * i40, s1y * i40);
        store_mean2(5120 + (size_t)dia * 3 + 2, c, s2x * i40, s2y * i40);
        store_mean2(5504 + (size_t)dia, c, (s0x + s1x + s2x) * i120, (s0y + s1y + s2y) * i120);
    } else {
        int c = tid * 2;
        size_t o = (size_t)19456 * NHID + c;
        float2 v  = *(const float2*)(g_outA + o);
        float2 b2 = *(const float2*)(convb + NHID + c);
        split1(v.x + b2.x, g_oAhi[o],     g_oAlo[o]);
        split1(v.y + b2.y, g_oAhi[o + 1], g_oAlo[o + 1]);
    }
}

// ---------------------------------------------------------------------------
// Combos of M_j (from g_Mout) -> B-format splits:
// z0 M0^T; z1 (MT-M0)^T; z2 (MB-M0)^T; z3 (M0-MB-MT+MG)^T
// ---------------------------------------------------------------------------
__global__ void combo_xpose_kernel()
{
    __shared__ float tile[32][33];
    const float CF[4][4] = { {1,0,0,0}, {-1,0,1,0}, {-1,1,0,0}, {1,-1,-1,1} };
    int z = blockIdx.z;
    int c0 = blockIdx.x * 32, r0 = blockIdx.y * 32;
    #pragma unroll
    for (int i = 0; i < 32; i += 8) {
        size_t rc = (size_t)(r0 + threadIdx.y + i) * NHID + c0 + threadIdx.x;
        float v = 0.f;
        #pragma unroll
        for (int j = 0; j < 4; j++)
            if (CF[z][j] != 0.f) v += CF[z][j] * g_Mout[(size_t)j * 512 * NHID + rc];
        tile[threadIdx.y + i][threadIdx.x] = v;
    }
    __syncthreads();
    #pragma unroll
    for (int i = 0; i < 32; i += 8) {
        size_t o = (size_t)z * MM + (size_t)(c0 + threadIdx.y + i) * NHID + r0 + threadIdx.x;
        split1(tile[threadIdx.x][threadIdx.y + i], g_cbhi[o], g_cblo[o]);
    }
}

// ---------------------------------------------------------------------------
// Combine + assemble. dd = d0 + bb3 + b4.
// ---------------------------------------------------------------------------
__global__ void combine_kernel(const float* __restrict__ convb, float* __restrict__ out)
{
    int idx = blockIdx.x * blockDim.x + threadIdx.x;
    if (idx >= N_NODE * 128) return;
    int c    = (idx & 127) * 4;
    int node = idx >> 7;
    int dia  = node / ROWS_PER_DIA;
    int r    = node - dia * ROWS_PER_DIA;
    int m    = r / L_DIA;
    int t    = r - m * L_DIA;
    int u    = dia * L_DIA + t;

    float4 f  = *(const float4*)(g_feats + (size_t)node * NHID + c);
    float4 x1 = *(const float4*)(g_outA + (size_t)node * NHID + c);
    float4 ga = *(const float4*)(g_gnn + (size_t)node * NHID + c);
    float4 gt = *(const float4*)(g_gnn + (size_t)(15360 + dia * L_DIA + t) * NHID + c);
    float4 gb = *(const float4*)(g_gnn + (size_t)(20480 + dia * 3 + m) * NHID + c);
    float4 gg = *(const float4*)(g_gnn + (size_t)(20864 + dia) * NHID + c);
    float4 d0 = *(const float4*)(g_Mout + (size_t)2048 * NHID + c);
    float4 b3r = *(const float4*)(g_outA + (size_t)19584 * NHID + c);
    float4 b4 = *(const float4*)(convb + 3 * NHID + c);

    float4 gnn = make_float4(
        ga.x + gt.x + gb.x + gg.x + d0.x + b3r.x + b4.x,
        ga.y + gt.y + gb.y + gg.y + d0.y + b3r.y + b4.y,
        ga.z + gt.z + gb.z + gg.z + d0.z + b3r.z + b4.z,
        ga.w + gt.w + gb.w + gg.w + d0.w + b3r.w + b4.w);

    float* o = out + (size_t)u * OUT_COLS + m * OUT_D2 + c;
    *(float4*)(o)        = f;
    *(float4*)(o + 512)  = x1;
    *(float4*)(o + 1024) = gnn;
}

// ---------------------------------------------------------------------------
extern "C" void kernel_launch(void* const* d_in, const int* in_sizes, int n_in,
                              void* d_out, int out_size)
{
    const float* a      = (const float*)d_in[0];
    const float* v      = (const float*)d_in[1];
    const float* l      = (const float*)d_in[2];
    const float* qmask  = (const float*)d_in[3];
    const float* spk    = (const float*)d_in[4];
    const float* fc1_W  = (const float*)d_in[5];
    const float* fc1_b  = (const float*)d_in[6];
    const float* convW  = (const float*)d_in[7];
    const float* convb  = (const float*)d_in[8];
    float* out = (float*)d_out;

    __half *w0hi, *w0lo, *fahi, *falo, *oAhi, *oAlo, *Afhi, *Aflo;
    __half *Bfhi, *Bflo, *P2Thi, *P2Tlo, *mhi, *mlo, *cbhi, *cblo;
    float *outA, *Mout, *gnn;
    cudaGetSymbolAddress((void**)&w0hi, g_w0hi);   cudaGetSymbolAddress((void**)&w0lo, g_w0lo);
    cudaGetSymbolAddress((void**)&fahi, g_fahi);   cudaGetSymbolAddress((void**)&falo, g_falo);
    cudaGetSymbolAddress((void**)&oAhi, g_oAhi);   cudaGetSymbolAddress((void**)&oAlo, g_oAlo);
    cudaGetSymbolAddress((void**)&Afhi, g_Afhi);   cudaGetSymbolAddress((void**)&Aflo, g_Aflo);
    cudaGetSymbolAddress((void**)&Bfhi, g_Bfhi);   cudaGetSymbolAddress((void**)&Bflo, g_Bflo);
    cudaGetSymbolAddress((void**)&P2Thi, g_P2Thi); cudaGetSymbolAddress((void**)&P2Tlo, g_P2Tlo);
    cudaGetSymbolAddress((void**)&mhi, g_mhi);     cudaGetSymbolAddress((void**)&mlo, g_mlo);
    cudaGetSymbolAddress((void**)&cbhi, g_cbhi);   cudaGetSymbolAddress((void**)&cblo, g_cblo);
    cudaGetSymbolAddress((void**)&outA, g_outA);
    cudaGetSymbolAddress((void**)&Mout, g_Mout);
    cudaGetSymbolAddress((void**)&gnn, g_gnn);

    cudaFuncSetAttribute(gemm_u, cudaFuncAttributeMaxDynamicSharedMemorySize, GEMM_SMEM_BYTES);

    const int BIG = 1 << 20;

    // 1. transpose weights (f32 all, splits for fc1)
    transpose_split_kernel<<<dim3(16, 16, 5), dim3(32, 8)>>>(fc1_W, convW);
    // 2. prep factors + zero Mout
    prep_kernel<<<(PREP_TOTAL + 255) / 256, 256>>>(convW, convb);
    // 3. features
    build_feats_kernel<<<(N_NODE * 128 + 255) / 256, 256>>>(a, v, l, qmask, spk);

    // 4. MEGA-A: x1 (2-pass) + pairwise products + bias rows (3-pass)
    {
        GP p{};
        p.Ahi0 = fahi; p.Alo0 = falo;
        p.Ahi1 = Afhi; p.Alo1 = Aflo;
        p.aSwitchY = 120; p.aRowOfs0 = 0; p.aRowOfs1 = 15360;
        const int ys[11]   = { 0, 120, 124, 128, 132, 136, 140, 144, 148, 152, 153 };
        const int bofs[11] = { -1, 0, 1, 2, 3, 4, 5, 6, 7, 3, 7 };
        for (int i = 0; i < 11; i++) {
            p.yStart[i] = ys[i];
            if (i == 0) { p.Bhi[i] = w0hi; p.Blo[i] = w0lo; }
            else        { p.Bhi[i] = Bfhi + (size_t)bofs[i] * MM; p.Blo[i] = Bflo + (size_t)bofs[i] * MM; }
        }
        p.bias[0] = fc1_b;
        p.C = outA; p.Chi = oAhi; p.Clo = oAlo;
        p.splitK = 0;
        p.kt16mask = 0x1;                 // region 0 (x1) 2-pass; products 3-pass
        gemm_u<<<dim3(4, OUTA_ROWS / 128), 256, GEMM_SMEM_BYTES>>>(p);
    }

    // 5. misc: P2 transpose-splits + means + dA row
    misc_kernel<<<1153, 256>>>(convb);

    // 6. step B: M_j = P1_j * P2_j and d0 = dA * P2_3  (split-K 3-pass)
    {
        GP p{};
        p.Ahi0 = oAhi; p.Alo0 = oAlo;
        p.Ahi1 = oAhi; p.Alo1 = oAlo;
        p.aSwitchY = 16; p.aRowOfs0 = -15360; p.aRowOfs1 = -17408;
        const int ys[11]   = { 0, 4, 8, 12, 16, BIG, BIG, BIG, BIG, BIG, BIG };
        const int bofs[11] = { 0, 1, 2, 3, 3, 3, 3, 3, 3, 3, 3 };
        for (int i = 0; i < 11; i++) {
            p.yStart[i] = ys[i];
            p.Bhi[i] = P2Thi + (size_t)bofs[i] * MM;
            p.Blo[i] = P2Tlo + (size_t)bofs[i] * MM;
        }
        p.C = Mout; p.Chi = nullptr; p.Clo = nullptr;
        p.splitK = 1;
        p.kt16mask = 0;
        gemm_u<<<dim3(4, MOUT_ROWS / 128, 3), 256, GEMM_SMEM_BYTES>>>(p);
    }

    // 7. combos -> B-format
    combo_xpose_kernel<<<dim3(16, 16, 4), dim3(32, 8)>>>();

    // 8. MEGA-gnn (all 2-pass)
    {
        GP p{};
        p.Ahi0 = oAhi; p.Alo0 = oAlo;
        p.Ahi1 = mhi;  p.Alo1 = mlo;
        p.aSwitchY = 120; p.aRowOfs0 = 0; p.aRowOfs1 = 15360;
        const int ys[11] = { 0, 120, 160, 163, BIG, BIG, BIG, BIG, BIG, BIG, BIG };
        for (int i = 0; i < 11; i++) {
            p.yStart[i] = ys[i];
            int bi = (i < 4) ? i : 3;
            p.Bhi[i] = cbhi + (size_t)bi * MM;
            p.Blo[i] = cblo + (size_t)bi * MM;
        }
        p.C = gnn; p.Chi = nullptr; p.Clo = nullptr;
        p.splitK = 0;
        p.kt16mask = 0x7FF;
        gemm_u<<<dim3(4, GNN_ROWS / 128), 256, GEMM_SMEM_BYTES>>>(p);
    }

    // 9. combine + assemble
    combine_kernel<<<(N_NODE * 128 + 255) / 256, 256>>>(convb, out);
    (void)in_sizes; (void)n_in; (void)out_size;
}

// round 14
// speedup vs baseline: 2.7037x; 1.1752x over previous
#include <cuda_runtime.h>
#include <cuda_fp16.h>
#include <cstdint>

#define D_DIA   128
#define L_DIA   40
#define NHID    512
#define N_UTT   5120
#define N_NODE  15360
#define ROWS_PER_DIA 120
#define OUT_D2  1536
#define OUT_COLS 4608
#define MM      (NHID * NHID)

// GEMM config: BK=64 (128B rows, XOR swizzle), fp16, 1/2/3 precision passes
#define BM 128
#define BN 128
#define TILE_BYTES (128 * 128)
#define STAGE_BYTES (2 * TILE_BYTES)
#define GEMM_SMEM_BYTES (3 * STAGE_BYTES)   // 96 KB

// outA layout (rows): x1 0..15359 | P1_j 15360+512j | P2_j 17408+512j | bb1 19456 | bb3 19584
#define OUTA_ROWS 19712
#define AFAC_ROWS 4352    // G1_j(2048) G3_j(2048) b1-tile(128@4096) b3-tile(128@4224)
#define MOUT_ROWS 2176    // M_j(2048) + d-tile(128@2048)
#define MEAN_ROWS 5632    // ft(5120) fb(384) fg(128)
#define GNN_ROWS  20992   // node(15360) ft(5120) fb(384) fg(128)

// ---------------------------------------------------------------------------
__device__ float g_feats[N_NODE * NHID];
__device__ __half g_fahi[N_NODE * NHID], g_falo[N_NODE * NHID];
__device__ float g_wtf[5 * MM];                 // W^T f32 (w0 fc1, w1..4 conv)
__device__ __half g_w0hi[MM], g_w0lo[MM];       // fc1 W^T splits
__device__ float g_outA[OUTA_ROWS * NHID];
__device__ __half g_oAhi[OUTA_ROWS * NHID], g_oAlo[OUTA_ROWS * NHID];
__device__ __half g_Afhi[AFAC_ROWS * NHID], g_Aflo[AFAC_ROWS * NHID];
__device__ __half g_Bfhi[8 * MM], g_Bflo[8 * MM];   // F2_j(4), F4_j(4) B-format
__device__ __half g_P2Thi[4 * MM], g_P2Tlo[4 * MM];
__device__ float g_Mout[MOUT_ROWS * NHID];
__device__ float g_means[MEAN_ROWS * NHID];
__device__ __half g_mhi[MEAN_ROWS * NHID], g_mlo[MEAN_ROWS * NHID];
__device__ __half g_cbhi[4 * MM], g_cblo[4 * MM];
__device__ float g_gnn[GNN_ROWS * NHID];

// ---------------------------------------------------------------------------
__device__ __forceinline__ uint32_t smem_u32(const void* p) {
    uint32_t a;
    asm("{ .reg .u64 t; cvta.to.shared.u64 t, %1; cvt.u32.u64 %0, t; }" : "=r"(a) : "l"(p));
    return a;
}
__device__ __forceinline__ void cp16(uint32_t d, const void* g) {
    asm volatile("cp.async.cg.shared.global [%0], [%1], 16;" :: "r"(d), "l"(g));
}
__device__ __forceinline__ void ldsm4(uint32_t* r, uint32_t addr) {
    asm volatile("ldmatrix.sync.aligned.m8n8.x4.shared.b16 {%0,%1,%2,%3}, [%4];"
        : "=r"(r[0]), "=r"(r[1]), "=r"(r[2]), "=r"(r[3]) : "r"(addr));
}
__device__ __forceinline__ void mma_f16(float* d, const uint32_t* a, uint32_t b0, uint32_t b1) {
    asm volatile("mma.sync.aligned.m16n8k16.row.col.f32.f16.f16.f32 "
        "{%0,%1,%2,%3}, {%4,%5,%6,%7}, {%8,%9}, {%0,%1,%2,%3};"
        : "+f"(d[0]), "+f"(d[1]), "+f"(d[2]), "+f"(d[3])
        : "r"(a[0]), "r"(a[1]), "r"(a[2]), "r"(a[3]), "r"(b0), "r"(b1));
}
__device__ __forceinline__ void split1(float v, __half& h, __half& l) {
    h = __float2half_rn(v);
    l = __float2half_rn(v - __half2float(h));
}

// ---------------------------------------------------------------------------
// Unified GEMM, 11 y-regions: C = A*B[reg] (+bias[reg]); A ptr/ofs switches at
// aSwitchY. npass[reg] in {1,2,3}: p0 Ahi*Bhi; p1 = Ahi*Blo (3p) / Alo*Bhi (2p);
// p2 = Alo*Bhi (3p).  splitK: blockIdx.z = pass (3-pass), 8 k-iters, atomicAdd.
// ---------------------------------------------------------------------------
struct GP {
    const __half *Ahi0, *Alo0, *Ahi1, *Alo1;
    int aSwitchY, aRowOfs0, aRowOfs1;
    const __half *Bhi[11], *Blo[11];
    const float* bias[11];
    int yStart[11];
    float* C;
    __half *Chi, *Clo;
    int splitK;
    int npass[11];
};

__global__ __launch_bounds__(256, 2)
void gemm_u(GP gp)
{
    extern __shared__ char smem[];
    const uint32_t smem0 = smem_u32(smem);
    const int tid  = threadIdx.x;
    const int lane = tid & 31;
    const int wid  = tid >> 5;
    const int warp_m = wid & 3, warp_n = wid >> 2;
    const int bm = blockIdx.y * BM, bn = blockIdx.x * BN;

    int reg = 0;
    #pragma unroll
    for (int i = 1; i < 11; i++) if ((int)blockIdx.y >= gp.yStart[i]) reg = i;
    const float* bias = gp.bias[reg];

    const __half *Ahi, *Alo;
    int arow;
    if ((int)blockIdx.y >= gp.aSwitchY) { Ahi = gp.Ahi1; Alo = gp.Alo1; arow = bm - gp.aRowOfs1; }
    else                                { Ahi = gp.Ahi0; Alo = gp.Alo0; arow = bm - gp.aRowOfs0; }

    float acc[2][8][4];
    #pragma unroll
    for (int i = 0; i < 2; i++)
        #pragma unroll
        for (int j = 0; j < 8; j++)
            #pragma unroll
            for (int q = 0; q < 4; q++) acc[i][j][q] = 0.f;

    const char* AhiP = (const char*)Ahi + (size_t)arow * 1024;
    const char* AloP = (const char*)Alo + (size_t)arow * 1024;
    const char* BhiP = (const char*)gp.Bhi[reg] + (size_t)bn * 1024;
    const char* BloP = (const char*)gp.Blo[reg] + (size_t)bn * 1024;

    const int np = gp.splitK ? 3 : gp.npass[reg];
    const int ktTot = gp.splitK ? 8 : np * 8;
    const int zpass = gp.splitK ? (int)blockIdx.z : -1;

    auto load_tile = [&](int kt, int s) {
        int p = (zpass >= 0) ? zpass : (kt >> 3);
        bool useAlo = (np == 3) ? (p == 2) : (p >= 1);
        bool useBlo = (np == 3) && (p == 1);
        const char* Ag = (useAlo ? AloP : AhiP) + (kt & 7) * 128;
        const char* Bg = (useBlo ? BloP : BhiP) + (kt & 7) * 128;
        uint32_t sa = smem0 + s * STAGE_BYTES;
        #pragma unroll
        for (int i = 0; i < 4; i++) {
            int ci  = i * 256 + tid;
            int row = ci >> 3;
            int c16 = ci & 7;
            uint32_t so = (uint32_t)row * 128 + (uint32_t)((c16 ^ (row & 7)) * 16);
            cp16(sa + so, Ag + (size_t)row * 1024 + c16 * 16);
            cp16(sa + TILE_BYTES + so, Bg + (size_t)row * 1024 + c16 * 16);
        }
        asm volatile("cp.async.commit_group;" ::: "memory");
    };

    const int half_ = lane >> 4;
    const int lx    = lane & 7;
    const uint32_t aOff = (uint32_t)(warp_m * 32 + (lane & 15)) * 128;
    const uint32_t bOff = (uint32_t)(warp_n * 64 + (lane & 15)) * 128;

    load_tile(0, 0);
    if (ktTot > 1) load_tile(1, 1);
    else asm volatile("cp.async.commit_group;" ::: "memory");

    for (int kt = 0; kt < ktTot; kt++) {
        int s = kt % 3;
        asm volatile("cp.async.wait_group 1;" ::: "memory");
        __syncthreads();
        if (kt + 2 < ktTot) load_tile(kt + 2, (kt + 2) % 3);
        else asm volatile("cp.async.commit_group;" ::: "memory");

        const uint32_t sbase = smem0 + (uint32_t)s * STAGE_BYTES;
        #pragma unroll
        for (int k16 = 0; k16 < 4; k16++) {
            const uint32_t co = (uint32_t)(((2 * k16 + half_) ^ lx) * 16);
            uint32_t a0[4], a1[4];
            ldsm4(a0, sbase + aOff + co);
            ldsm4(a1, sbase + aOff + 2048 + co);
            #pragma unroll
            for (int q = 0; q < 4; q++) {
                uint32_t b[4];
                ldsm4(b, sbase + TILE_BYTES + bOff + (uint32_t)q * 2048 + co);
                mma_f16(acc[0][2 * q + 0], a0, b[0], b[2]);
                mma_f16(acc[0][2 * q + 1], a0, b[1], b[3]);
                mma_f16(acc[1][2 * q + 0], a1, b[0], b[2]);
                mma_f16(acc[1][2 * q + 1], a1, b[1], b[3]);
            }
        }
    }

    const int m0 = bm + warp_m * 32;
    const int n0 = bn + warp_n * 64;
    #pragma unroll
    for (int mt = 0; mt < 2; mt++) {
        int r0 = m0 + mt * 16 + (lane >> 2);
        #pragma unroll
        for (int nt = 0; nt < 8; nt++) {
            int col = n0 + nt * 8 + (lane & 3) * 2;
            size_t o0 = (size_t)r0 * NHID + col;
            size_t o1 = (size_t)(r0 + 8) * NHID + col;
            if (gp.splitK) {
                atomicAdd(gp.C + o0,     acc[mt][nt][0]);
                atomicAdd(gp.C + o0 + 1, acc[mt][nt][1]);
                atomicAdd(gp.C + o1,     acc[mt][nt][2]);
                atomicAdd(gp.C + o1 + 1, acc[mt][nt][3]);
            } else {
                float2 v0 = make_float2(acc[mt][nt][0], acc[mt][nt][1]);
                float2 v1 = make_float2(acc[mt][nt][2], acc[mt][nt][3]);
                if (bias) {
                    float bx = bias[col], by = bias[col + 1];
                    v0.x += bx; v0.y += by; v1.x += bx; v1.y += by;
                }
                *(float2*)(gp.C + o0) = v0;
                *(float2*)(gp.C + o1) = v1;
                if (gp.Chi) {
                    __half h, l;
                    split1(v0.x, h, l); gp.Chi[o0] = h;     gp.Clo[o0] = l;
                    split1(v0.y, h, l); gp.Chi[o0 + 1] = h; gp.Clo[o0 + 1] = l;
                    split1(v1.x, h, l); gp.Chi[o1] = h;     gp.Clo[o1] = l;
                    split1(v1.y, h, l); gp.Chi[o1 + 1] = h; gp.Clo[o1 + 1] = l;
                }
            }
        }
    }
}

// ---------------------------------------------------------------------------
// Weight transpose: wtf[w][n][k] = W[w][k][n] (f32); splits only for w=0.
// ---------------------------------------------------------------------------
__global__ void transpose_split_kernel(const float* __restrict__ fc1W,
                                       const float* __restrict__ convW)
{
    __shared__ float tile[32][33];
    int w = blockIdx.z;
    const float* W = (w == 0) ? fc1W : convW + (size_t)(w - 1) * MM;
    int n0 = blockIdx.x * 32, k0 = blockIdx.y * 32;
    #pragma unroll
    for (int i = 0; i < 32; i += 8)
        tile[threadIdx.y + i][threadIdx.x] = W[(size_t)(k0 + threadIdx.y + i) * NHID + n0 + threadIdx.x];
    __syncthreads();
    #pragma unroll
    for (int i = 0; i < 32; i += 8) {
        float v = tile[threadIdx.x][threadIdx.y + i];
        size_t o = (size_t)w * MM + (size_t)(n0 + threadIdx.y + i) * NHID + k0 + threadIdx.x;
        g_wtf[o] = v;
        if (w == 0) split1(v, g_w0hi[o], g_w0lo[o]);
    }
}

// ---------------------------------------------------------------------------
// Prep: A-factors G1_j=I+λjC1, G3_j=I+λjC3 (+b1/b3 rows, zero pad), B-factors
// F2_j=(I+λjC2)^T, F4_j=(I+λjC4)^T, and zero Mout.
// ---------------------------------------------------------------------------
#define A_ELEMS (AFAC_ROWS * NHID)
#define B_ELEMS (8 * MM)
#define PREP_TOTAL (A_ELEMS + B_ELEMS + MOUT_ROWS * NHID)

__global__ void prep_kernel(const float* __restrict__ convW,
                            const float* __restrict__ convb)
{
    int idx = blockIdx.x * blockDim.x + threadIdx.x;
    if (idx >= PREP_TOTAL) return;
    const float L[4] = { -1.f / 42.f, 39.f / 42.f, 2.f / 42.f, 1.f };
    if (idx < A_ELEMS) {
        int r = idx >> 9, c = idx & 511;
        float v = 0.f;
        if (r < 2048) {
            int rr = r & 511;
            v = L[r >> 9] * convW[(size_t)rr * NHID + c] + ((rr == c) ? 1.f : 0.f);
        } else if (r < 4096) {
            int r2 = r - 2048, rr = r2 & 511;
            v = L[r2 >> 9] * convW[2 * (size_t)MM + (size_t)rr * NHID + c] + ((rr == c) ? 1.f : 0.f);
        } else if (r == 4096) v = convb[c];
        else if (r == 4224) v = convb[2 * NHID + c];
        split1(v, g_Afhi[idx], g_Aflo[idx]);
    } else if (idx < A_ELEMS + B_ELEMS) {
        int i = idx - A_ELEMS;
        int g = i >> 18;
        int nk = i & (MM - 1);
        int n = nk >> 9, k = nk & 511;
        int j = g & 3;
        int w = (g < 4) ? 2 : 4;          // C2^T or C4^T in wtf
        float v = L[j] * g_wtf[(size_t)w * MM + nk] + ((n == k) ? 1.f : 0.f);
        split1(v, g_Bfhi[i], g_Bflo[i]);
    } else {
        g_Mout[idx - A_ELEMS - B_ELEMS] = 0.f;
    }
}

// ---------------------------------------------------------------------------
// Build node features + splits
// ---------------------------------------------------------------------------
__global__ void build_feats_kernel(const float* __restrict__ a,
                                   const float* __restrict__ v,
                                   const float* __restrict__ l,
                                   const float* __restrict__ qmask,
                                   const float* __restrict__ spk)
{
    int idx = blockIdx.x * blockDim.x + threadIdx.x;
    if (idx >= N_NODE * 128) return;
    int c    = (idx & 127) * 4;
    int node = idx >> 7;
    int dia  = node / ROWS_PER_DIA;
    int r    = node - dia * ROWS_PER_DIA;
    int m    = r / L_DIA;
    int t    = r - m * L_DIA;
    int u    = dia * L_DIA + t;

    float4 val;
    if (m == 0) {
        float q0 = qmask[(t * D_DIA + dia) * 2 + 0];
        float q1 = qmask[(t * D_DIA + dia) * 2 + 1];
        int s = (q1 > q0) ? 1 : 0;
        float4 lv = *(const float4*)(l + (size_t)u * NHID + c);
        float4 sv = *(const float4*)(spk + (size_t)s * NHID + c);
        val = make_float4(lv.x + sv.x, lv.y + sv.y, lv.z + sv.z, lv.w + sv.w);
    } else if (m == 1) {
        val = *(const float4*)(a + (size_t)u * NHID + c);
    } else {
        val = *(const float4*)(v + (size_t)u * NHID + c);
    }
    size_t o = (size_t)node * NHID + c;
    *(float4*)(g_feats + o) = val;
    split1(val.x, g_fahi[o],     g_falo[o]);
    split1(val.y, g_fahi[o + 1], g_falo[o + 1]);
    split1(val.z, g_fahi[o + 2], g_falo[o + 2]);
    split1(val.w, g_fahi[o + 3], g_falo[o + 3]);
}

// ---------------------------------------------------------------------------
// Misc (one launch): [0,1024) transpose P2_j -> B-splits; [1024,1152) means;
// [1152] dA row = bb1 + b2 -> splits into outA row 19456.
// ---------------------------------------------------------------------------
__device__ __forceinline__ void store_mean2(size_t row, int c, float x, float y)
{
    size_t o = row * NHID + c;
    g_means[o] = x; g_means[o + 1] = y;
    split1(x, g_mhi[o],     g_mlo[o]);
    split1(y, g_mhi[o + 1], g_mlo[o + 1]);
}

__global__ void misc_kernel(const float* __restrict__ convb)
{
    __shared__ float tile[32][33];
    int b = blockIdx.x, tid = threadIdx.x;
    if (b < 1024) {
        int z = b >> 8, t = b & 255;
        int r0 = (t >> 4) * 32, c0 = (t & 15) * 32;
        int tx = tid & 31, ty = tid >> 5;
        #pragma unroll
        for (int i = 0; i < 32; i += 8)
            tile[ty + i][tx] = g_outA[(size_t)(17408 + z * 512 + r0 + ty + i) * NHID + c0 + tx];
        __syncthreads();
        #pragma unroll
        for (int i = 0; i < 32; i += 8) {
            size_t o = (size_t)z * MM + (size_t)(c0 + ty + i) * NHID + r0 + tx;
            split1(tile[tx][ty + i], g_P2Thi[o], g_P2Tlo[o]);
        }
    } else if (b < 1152) {
        int dia = b - 1024;
        int c = tid * 2;
        const float* xb = g_outA + (size_t)dia * ROWS_PER_DIA * NHID;
        float s0x = 0, s0y = 0, s1x = 0, s1y = 0, s2x = 0, s2y = 0;
        for (int t = 0; t < L_DIA; t++) {
            float2 v0 = *(const float2*)(xb + (size_t)t * NHID + c);
            float2 v1 = *(const float2*)(xb + (size_t)(L_DIA + t) * NHID + c);
            float2 v2 = *(const float2*)(xb + (size_t)(2 * L_DIA + t) * NHID + c);
            s0x += v0.x; s0y += v0.y;
            s1x += v1.x; s1y += v1.y;
            s2x += v2.x; s2y += v2.y;
            const float i3 = 1.f / 3.f;
            store_mean2((size_t)dia * L_DIA + t, c,
                        (v0.x + v1.x + v2.x) * i3, (v0.y + v1.y + v2.y) * i3);
        }
        const float i40 = 1.f / 40.f, i120 = 1.f / 120.f;
        store_mean2(5120 + (size_t)dia * 3 + 0, c, s0x * i40, s0y * i40);
        store_mean2(5120 + (size_t)dia * 3 + 1, c, s1x * i40, s1y * i40);
        store_mean2(5120 + (size_t)dia * 3 + 2, c, s2x * i40, s2y * i40);
        store_mean2(5504 + (size_t)dia, c, (s0x + s1x + s2x) * i120, (s0y + s1y + s2y) * i120);
    } else {
        int c = tid * 2;
        size_t o = (size_t)19456 * NHID + c;
        float2 v  = *(const float2*)(g_outA + o);
        float2 b2 = *(const float2*)(convb + NHID + c);
        split1(v.x + b2.x, g_oAhi[o],     g_oAlo[o]);
        split1(v.y + b2.y, g_oAhi[o + 1], g_oAlo[o + 1]);
    }
}

// ---------------------------------------------------------------------------
// Combos of M_j (from g_Mout) -> B-format splits:
// z0 M0^T; z1 (MT-M0)^T; z2 (MB-M0)^T; z3 (M0-MB-MT+MG)^T
// ---------------------------------------------------------------------------
__global__ void combo_xpose_kernel()
{
    __shared__ float tile[32][33];
    const float CF[4][4] = { {1,0,0,0}, {-1,0,1,0}, {-1,1,0,0}, {1,-1,-1,1} };
    int z = blockIdx.z;
    int c0 = blockIdx.x * 32, r0 = blockIdx.y * 32;
    #pragma unroll
    for (int i = 0; i < 32; i += 8) {
        size_t rc = (size_t)(r0 + threadIdx.y + i) * NHID + c0 + threadIdx.x;
        float v = 0.f;
        #pragma unroll
        for (int j = 0; j < 4; j++)
            if (CF[z][j] != 0.f) v += CF[z][j] * g_Mout[(size_t)j * 512 * NHID + rc];
        tile[threadIdx.y + i][threadIdx.x] = v;
    }
    __syncthreads();
    #pragma unroll
    for (int i = 0; i < 32; i += 8) {
        size_t o = (size_t)z * MM + (size_t)(c0 + threadIdx.y + i) * NHID + r0 + threadIdx.x;
        split1(tile[threadIdx.x][threadIdx.y + i], g_cbhi[o], g_cblo[o]);
    }
}

// ---------------------------------------------------------------------------
// Combine + assemble. dd = d0 + bb3 + b4.
// ---------------------------------------------------------------------------
__global__ void combine_kernel(const float* __restrict__ convb, float* __restrict__ out)
{
    int idx = blockIdx.x * blockDim.x + threadIdx.x;
    if (idx >= N_NODE * 128) return;
    int c    = (idx & 127) * 4;
    int node = idx >> 7;
    int dia  = node / ROWS_PER_DIA;
    int r    = node - dia * ROWS_PER_DIA;
    int m    = r / L_DIA;
    int t    = r - m * L_DIA;
    int u    = dia * L_DIA + t;

    float4 f  = *(const float4*)(g_feats + (size_t)node * NHID + c);
    float4 x1 = *(const float4*)(g_outA + (size_t)node * NHID + c);
    float4 ga = *(const float4*)(g_gnn + (size_t)node * NHID + c);
    float4 gt = *(const float4*)(g_gnn + (size_t)(15360 + dia * L_DIA + t) * NHID + c);
    float4 gb = *(const float4*)(g_gnn + (size_t)(20480 + dia * 3 + m) * NHID + c);
    float4 gg = *(const float4*)(g_gnn + (size_t)(20864 + dia) * NHID + c);
    float4 d0 = *(const float4*)(g_Mout + (size_t)2048 * NHID + c);
    float4 b3r = *(const float4*)(g_outA + (size_t)19584 * NHID + c);
    float4 b4 = *(const float4*)(convb + 3 * NHID + c);

    float4 gnn = make_float4(
        ga.x + gt.x + gb.x + gg.x + d0.x + b3r.x + b4.x,
        ga.y + gt.y + gb.y + gg.y + d0.y + b3r.y + b4.y,
        ga.z + gt.z + gb.z + gg.z + d0.z + b3r.z + b4.z,
        ga.w + gt.w + gb.w + gg.w + d0.w + b3r.w + b4.w);

    float* o = out + (size_t)u * OUT_COLS + m * OUT_D2 + c;
    *(float4*)(o)        = f;
    *(float4*)(o + 512)  = x1;
    *(float4*)(o + 1024) = gnn;
}

// ---------------------------------------------------------------------------
extern "C" void kernel_launch(void* const* d_in, const int* in_sizes, int n_in,
                              void* d_out, int out_size)
{
    const float* a      = (const float*)d_in[0];
    const float* v      = (const float*)d_in[1];
    const float* l      = (const float*)d_in[2];
    const float* qmask  = (const float*)d_in[3];
    const float* spk    = (const float*)d_in[4];
    const float* fc1_W  = (const float*)d_in[5];
    const float* fc1_b  = (const float*)d_in[6];
    const float* convW  = (const float*)d_in[7];
    const float* convb  = (const float*)d_in[8];
    float* out = (float*)d_out;

    __half *w0hi, *w0lo, *fahi, *falo, *oAhi, *oAlo, *Afhi, *Aflo;
    __half *Bfhi, *Bflo, *P2Thi, *P2Tlo, *mhi, *mlo, *cbhi, *cblo;
    float *outA, *Mout, *gnn;
    cudaGetSymbolAddress((void**)&w0hi, g_w0hi);   cudaGetSymbolAddress((void**)&w0lo, g_w0lo);
    cudaGetSymbolAddress((void**)&fahi, g_fahi);   cudaGetSymbolAddress((void**)&falo, g_falo);
    cudaGetSymbolAddress((void**)&oAhi, g_oAhi);   cudaGetSymbolAddress((void**)&oAlo, g_oAlo);
    cudaGetSymbolAddress((void**)&Afhi, g_Afhi);   cudaGetSymbolAddress((void**)&Aflo, g_Aflo);
    cudaGetSymbolAddress((void**)&Bfhi, g_Bfhi);   cudaGetSymbolAddress((void**)&Bflo, g_Bflo);
    cudaGetSymbolAddress((void**)&P2Thi, g_P2Thi); cudaGetSymbolAddress((void**)&P2Tlo, g_P2Tlo);
    cudaGetSymbolAddress((void**)&mhi, g_mhi);     cudaGetSymbolAddress((void**)&mlo, g_mlo);
    cudaGetSymbolAddress((void**)&cbhi, g_cbhi);   cudaGetSymbolAddress((void**)&cblo, g_cblo);
    cudaGetSymbolAddress((void**)&outA, g_outA);
    cudaGetSymbolAddress((void**)&Mout, g_Mout);
    cudaGetSymbolAddress((void**)&gnn, g_gnn);

    cudaFuncSetAttribute(gemm_u, cudaFuncAttributeMaxDynamicSharedMemorySize, GEMM_SMEM_BYTES);

    const int BIG = 1 << 20;

    // 1. transpose weights (f32 all, splits for fc1)
    transpose_split_kernel<<<dim3(16, 16, 5), dim3(32, 8)>>>(fc1_W, convW);
    // 2. prep factors + zero Mout
    prep_kernel<<<(PREP_TOTAL + 255) / 256, 256>>>(convW, convb);
    // 3. features
    build_feats_kernel<<<(N_NODE * 128 + 255) / 256, 256>>>(a, v, l, qmask, spk);

    // 4. MEGA-A: x1 (1-pass) + pairwise products + bias rows (3-pass)
    {
        GP p{};
        p.Ahi0 = fahi; p.Alo0 = falo;
        p.Ahi1 = Afhi; p.Alo1 = Aflo;
        p.aSwitchY = 120; p.aRowOfs0 = 0; p.aRowOfs1 = 15360;
        const int ys[11]   = { 0, 120, 124, 128, 132, 136, 140, 144, 148, 152, 153 };
        const int bofs[11] = { -1, 0, 1, 2, 3, 4, 5, 6, 7, 3, 7 };
        for (int i = 0; i < 11; i++) {
            p.yStart[i] = ys[i];
            p.npass[i] = (i == 0) ? 1 : 3;
            if (i == 0) { p.Bhi[i] = w0hi; p.Blo[i] = w0lo; }
            else        { p.Bhi[i] = Bfhi + (size_t)bofs[i] * MM; p.Blo[i] = Bflo + (size_t)bofs[i] * MM; }
        }
        p.bias[0] = fc1_b;
        p.C = outA; p.Chi = oAhi; p.Clo = oAlo;
        p.splitK = 0;
        gemm_u<<<dim3(4, OUTA_ROWS / 128), 256, GEMM_SMEM_BYTES>>>(p);
    }

    // 5. misc: P2 transpose-splits + means + dA row
    misc_kernel<<<1153, 256>>>(convb);

    // 6. step B: M_j = P1_j * P2_j and d0 = dA * P2_3  (split-K 3-pass)
    {
        GP p{};
        p.Ahi0 = oAhi; p.Alo0 = oAlo;
        p.Ahi1 = oAhi; p.Alo1 = oAlo;
        p.aSwitchY = 16; p.aRowOfs0 = -15360; p.aRowOfs1 = -17408;
        const int ys[11]   = { 0, 4, 8, 12, 16, BIG, BIG, BIG, BIG, BIG, BIG };
        const int bofs[11] = { 0, 1, 2, 3, 3, 3, 3, 3, 3, 3, 3 };
        for (int i = 0; i < 11; i++) {
            p.yStart[i] = ys[i];
            p.npass[i] = 3;
            p.Bhi[i] = P2Thi + (size_t)bofs[i] * MM;
            p.Blo[i] = P2Tlo + (size_t)bofs[i] * MM;
        }
        p.C = Mout; p.Chi = nullptr; p.Clo = nullptr;
        p.splitK = 1;
        gemm_u<<<dim3(4, MOUT_ROWS / 128, 3), 256, GEMM_SMEM_BYTES>>>(p);
    }

    // 7. combos -> B-format
    combo_xpose_kernel<<<dim3(16, 16, 4), dim3(32, 8)>>>();

    // 8. MEGA-gnn (all 1-pass)
    {
        GP p{};
        p.Ahi0 = oAhi; p.Alo0 = oAlo;
        p.Ahi1 = mhi;  p.Alo1 = mlo;
        p.aSwitchY = 120; p.aRowOfs0 = 0; p.aRowOfs1 = 15360;
        const int ys[11] = { 0, 120, 160, 163, BIG, BIG, BIG, BIG, BIG, BIG, BIG };
        for (int i = 0; i < 11; i++) {
            p.yStart[i] = ys[i];
            p.npass[i] = 1;
            int bi = (i < 4) ? i : 3;
            p.Bhi[i] = cbhi + (size_t)bi * MM;
            p.Blo[i] = cblo + (size_t)bi * MM;
        }
        p.C = gnn; p.Chi = nullptr; p.Clo = nullptr;
        p.splitK = 0;
        gemm_u<<<dim3(4, GNN_ROWS / 128), 256, GEMM_SMEM_BYTES>>>(p);
    }

    // 9. combine + assemble
    combine_kernel<<<(N_NODE * 128 + 255) / 256, 256>>>(convb, out);
    (void)in_sizes; (void)n_in; (void)out_size;
}

// round 17
// speedup vs baseline: 2.9996x; 1.1094x over previous
#include <cuda_runtime.h>
#include <cuda_fp16.h>
#include <cstdint>

#define D_DIA   128
#define L_DIA   40
#define NHID    512
#define N_UTT   5120
#define N_NODE  15360
#define ROWS_PER_DIA 120
#define OUT_D2  1536
#define OUT_COLS 4608
#define MM      (NHID * NHID)

// GEMM config: BK=64 (128B rows, XOR swizzle), fp16, 1/3 precision passes
#define BM 128
#define BN 128
#define TILE_BYTES (128 * 128)
#define STAGE_BYTES (2 * TILE_BYTES)
#define GEMM_SMEM_BYTES (3 * STAGE_BYTES)   // 96 KB

// outA layout (rows): P1_j 0+512j | P2_j 2048+512j | bb1-tile 4096 | bb3-tile 4224 | x1 4352..19711
#define X1_BASE  4352
#define OUTA_ROWS 19712
#define AFAC_ROWS 4352    // G1_j(2048) G3_j(2048) b1-tile(128@4096) b3-tile(128@4224)
#define MOUT_ROWS 2176    // M_j(2048) + d-tile(128@2048)
#define MEAN_ROWS 5632    // ft(5120) fb(384) fg(128)
#define GNN_ROWS  5632    // gt(5120) gb(384) gg(128)

// ---------------------------------------------------------------------------
__device__ float g_feats[N_NODE * NHID];
__device__ __half g_fahi[N_NODE * NHID];
__device__ float g_wtf[5 * MM];                 // W^T f32 (w0 fc1, w1..4 conv)
__device__ __half g_w0hi[MM], g_w0lo[MM];       // fc1 W^T splits
__device__ float g_outA[OUTA_ROWS * NHID];
__device__ __half g_oAhi[OUTA_ROWS * NHID], g_oAlo[OUTA_ROWS * NHID];
__device__ __half g_Afhi[AFAC_ROWS * NHID], g_Aflo[AFAC_ROWS * NHID];
__device__ __half g_Bfhi[8 * MM], g_Bflo[8 * MM];   // F2_j(4), F4_j(4) B-format
__device__ __half g_P2Thi[4 * MM], g_P2Tlo[4 * MM];
__device__ float g_Mout[MOUT_ROWS * NHID];
__device__ __half g_mhi[MEAN_ROWS * NHID];
__device__ __half g_cbhi[4 * MM], g_cblo[4 * MM];
__device__ float g_gnn[GNN_ROWS * NHID];
__device__ float g_ddv[NHID];

// ---------------------------------------------------------------------------
__device__ __forceinline__ uint32_t smem_u32(const void* p) {
    uint32_t a;
    asm("{ .reg .u64 t; cvta.to.shared.u64 t, %1; cvt.u32.u64 %0, t; }" : "=r"(a) : "l"(p));
    return a;
}
__device__ __forceinline__ void cp16(uint32_t d, const void* g) {
    asm volatile("cp.async.cg.shared.global [%0], [%1], 16;" :: "r"(d), "l"(g));
}
__device__ __forceinline__ void ldsm4(uint32_t* r, uint32_t addr) {
    asm volatile("ldmatrix.sync.aligned.m8n8.x4.shared.b16 {%0,%1,%2,%3}, [%4];"
        : "=r"(r[0]), "=r"(r[1]), "=r"(r[2]), "=r"(r[3]) : "r"(addr));
}
__device__ __forceinline__ void mma_f16(float* d, const uint32_t* a, uint32_t b0, uint32_t b1) {
    asm volatile("mma.sync.aligned.m16n8k16.row.col.f32.f16.f16.f32 "
        "{%0,%1,%2,%3}, {%4,%5,%6,%7}, {%8,%9}, {%0,%1,%2,%3};"
        : "+f"(d[0]), "+f"(d[1]), "+f"(d[2]), "+f"(d[3])
        : "r"(a[0]), "r"(a[1]), "r"(a[2]), "r"(a[3]), "r"(b0), "r"(b1));
}
__device__ __forceinline__ void split1(float v, __half& h, __half& l) {
    h = __float2half_rn(v);
    l = __float2half_rn(v - __half2float(h));
}

// ---------------------------------------------------------------------------
// Unified GEMM, 11 y-regions. npass[reg] in {1,3}. splitK: z = pass, atomicAdd.
// fuse: epilogue assembles final output (feats | x1 | gnn) directly.
// loSkipMask bit reg: skip Clo store for that region.
// ---------------------------------------------------------------------------
struct GP {
    const __half *Ahi0, *Alo0, *Ahi1, *Alo1;
    int aSwitchY, aRowOfs0, aRowOfs1;
    const __half *Bhi[11], *Blo[11];
    const float* bias[11];
    int yStart[11];
    float* C;                 // normal: C matrix; fuse: final out
    __half *Chi, *Clo;
    int splitK;
    int npass[11];
    int loSkipMask;
    int fuse;
    const float *gt, *ddv, *featsP, *x1P;   // fuse-mode inputs
};

__global__ __launch_bounds__(256, 2)
void gemm_u(GP gp)
{
    extern __shared__ char smem[];
    const uint32_t smem0 = smem_u32(smem);
    const int tid  = threadIdx.x;
    const int lane = tid & 31;
    const int wid  = tid >> 5;
    const int warp_m = wid & 3, warp_n = wid >> 2;
    const int bm = blockIdx.y * BM, bn = blockIdx.x * BN;

    int reg = 0;
    #pragma unroll
    for (int i = 1; i < 11; i++) if ((int)blockIdx.y >= gp.yStart[i]) reg = i;
    const float* bias = gp.bias[reg];

    const __half *Ahi, *Alo;
    int arow;
    if ((int)blockIdx.y >= gp.aSwitchY) { Ahi = gp.Ahi1; Alo = gp.Alo1; arow = bm - gp.aRowOfs1; }
    else                                { Ahi = gp.Ahi0; Alo = gp.Alo0; arow = bm - gp.aRowOfs0; }

    float acc[2][8][4];
    #pragma unroll
    for (int i = 0; i < 2; i++)
        #pragma unroll
        for (int j = 0; j < 8; j++)
            #pragma unroll
            for (int q = 0; q < 4; q++) acc[i][j][q] = 0.f;

    const char* AhiP = (const char*)Ahi + (size_t)arow * 1024;
    const char* AloP = (const char*)Alo + (size_t)arow * 1024;
    const char* BhiP = (const char*)gp.Bhi[reg] + (size_t)bn * 1024;
    const char* BloP = (const char*)gp.Blo[reg] + (size_t)bn * 1024;

    const int np = gp.splitK ? 3 : gp.npass[reg];
    const int ktTot = gp.splitK ? 8 : np * 8;
    const int zpass = gp.splitK ? (int)blockIdx.z : -1;

    auto load_tile = [&](int kt, int s) {
        int p = (zpass >= 0) ? zpass : (kt >> 3);
        bool useAlo = (p == 2);
        bool useBlo = (p == 1);
        const char* Ag = (useAlo ? AloP : AhiP) + (kt & 7) * 128;
        const char* Bg = (useBlo ? BloP : BhiP) + (kt & 7) * 128;
        uint32_t sa = smem0 + s * STAGE_BYTES;
        #pragma unroll
        for (int i = 0; i < 4; i++) {
            int ci  = i * 256 + tid;
            int row = ci >> 3;
            int c16 = ci & 7;
            uint32_t so = (uint32_t)row * 128 + (uint32_t)((c16 ^ (row & 7)) * 16);
            cp16(sa + so, Ag + (size_t)row * 1024 + c16 * 16);
            cp16(sa + TILE_BYTES + so, Bg + (size_t)row * 1024 + c16 * 16);
        }
        asm volatile("cp.async.commit_group;" ::: "memory");
    };

    const int half_ = lane >> 4;
    const int lx    = lane & 7;
    const uint32_t aOff = (uint32_t)(warp_m * 32 + (lane & 15)) * 128;
    const uint32_t bOff = (uint32_t)(warp_n * 64 + (lane & 15)) * 128;

    load_tile(0, 0);
    if (ktTot > 1) load_tile(1, 1);
    else asm volatile("cp.async.commit_group;" ::: "memory");

    for (int kt = 0; kt < ktTot; kt++) {
        int s = kt % 3;
        asm volatile("cp.async.wait_group 1;" ::: "memory");
        __syncthreads();
        if (kt + 2 < ktTot) load_tile(kt + 2, (kt + 2) % 3);
        else asm volatile("cp.async.commit_group;" ::: "memory");

        const uint32_t sbase = smem0 + (uint32_t)s * STAGE_BYTES;
        #pragma unroll
        for (int k16 = 0; k16 < 4; k16++) {
            const uint32_t co = (uint32_t)(((2 * k16 + half_) ^ lx) * 16);
            uint32_t a0[4], a1[4];
            ldsm4(a0, sbase + aOff + co);
            ldsm4(a1, sbase + aOff + 2048 + co);
            #pragma unroll
            for (int q = 0; q < 4; q++) {
                uint32_t b[4];
                ldsm4(b, sbase + TILE_BYTES + bOff + (uint32_t)q * 2048 + co);
                mma_f16(acc[0][2 * q + 0], a0, b[0], b[2]);
                mma_f16(acc[0][2 * q + 1], a0, b[1], b[3]);
                mma_f16(acc[1][2 * q + 0], a1, b[0], b[2]);
                mma_f16(acc[1][2 * q + 1], a1, b[1], b[3]);
            }
        }
    }

    const int m0 = bm + warp_m * 32;
    const int n0 = bn + warp_n * 64;

    if (gp.fuse) {
        // final-output epilogue: acc (node gnn part) + gt/gb/gg/dd; also feats, x1 thirds
        #pragma unroll
        for (int mt = 0; mt < 2; mt++) {
            #pragma unroll
            for (int rh = 0; rh < 2; rh++) {
                int r = m0 + mt * 16 + (lane >> 2) + rh * 8;
                int dia = r / ROWS_PER_DIA;
                int q   = r - dia * ROWS_PER_DIA;
                int m   = q / L_DIA;
                int t   = q - m * L_DIA;
                size_t ob = (size_t)(dia * L_DIA + t) * OUT_COLS + (size_t)m * OUT_D2;
                const float* gtP = gp.gt + (size_t)(dia * L_DIA + t) * NHID;
                const float* gbP = gp.gt + (size_t)(5120 + dia * 3 + m) * NHID;
                const float* ggP = gp.gt + (size_t)(5504 + dia) * NHID;
                const float* fP  = gp.featsP + (size_t)r * NHID;
                const float* xP  = gp.x1P + (size_t)r * NHID;
                #pragma unroll
                for (int nt = 0; nt < 8; nt++) {
                    int col = n0 + nt * 8 + (lane & 3) * 2;
                    float2 gv = make_float2(acc[mt][nt][rh * 2], acc[mt][nt][rh * 2 + 1]);
                    float2 a1v = *(const float2*)(gtP + col);
                    float2 a2v = *(const float2*)(gbP + col);
                    float2 a3v = *(const float2*)(ggP + col);
                    float2 a4v = *(const float2*)(gp.ddv + col);
                    gv.x += a1v.x + a2v.x + a3v.x + a4v.x;
                    gv.y += a1v.y + a2v.y + a3v.y + a4v.y;
                    *(float2*)(gp.C + ob + col)        = *(const float2*)(fP + col);
                    *(float2*)(gp.C + ob + 512 + col)  = *(const float2*)(xP + col);
                    *(float2*)(gp.C + ob + 1024 + col) = gv;
                }
            }
        }
        return;
    }

    const bool wrLo = (gp.Chi != nullptr) && !((gp.loSkipMask >> reg) & 1);
    #pragma unroll
    for (int mt = 0; mt < 2; mt++) {
        int r0 = m0 + mt * 16 + (lane >> 2);
        #pragma unroll
        for (int nt = 0; nt < 8; nt++) {
            int col = n0 + nt * 8 + (lane & 3) * 2;
            size_t o0 = (size_t)r0 * NHID + col;
            size_t o1 = (size_t)(r0 + 8) * NHID + col;
            if (gp.splitK) {
                atomicAdd(gp.C + o0,     acc[mt][nt][0]);
                atomicAdd(gp.C + o0 + 1, acc[mt][nt][1]);
                atomicAdd(gp.C + o1,     acc[mt][nt][2]);
                atomicAdd(gp.C + o1 + 1, acc[mt][nt][3]);
            } else {
                float2 v0 = make_float2(acc[mt][nt][0], acc[mt][nt][1]);
                float2 v1 = make_float2(acc[mt][nt][2], acc[mt][nt][3]);
                if (bias) {
                    float bx = bias[col], by = bias[col + 1];
                    v0.x += bx; v0.y += by; v1.x += bx; v1.y += by;
                }
                *(float2*)(gp.C + o0) = v0;
                *(float2*)(gp.C + o1) = v1;
                if (gp.Chi) {
                    __half h, l;
                    split1(v0.x, h, l); gp.Chi[o0] = h;     if (wrLo) gp.Clo[o0] = l;
                    split1(v0.y, h, l); gp.Chi[o0 + 1] = h; if (wrLo) gp.Clo[o0 + 1] = l;
                    split1(v1.x, h, l); gp.Chi[o1] = h;     if (wrLo) gp.Clo[o1] = l;
                    split1(v1.y, h, l); gp.Chi[o1 + 1] = h; if (wrLo) gp.Clo[o1 + 1] = l;
                }
            }
        }
    }
}

// ---------------------------------------------------------------------------
// Weight transpose: wtf[w][n][k] = W[w][k][n] (f32); splits only for w=0.
// ---------------------------------------------------------------------------
__global__ void transpose_split_kernel(const float* __restrict__ fc1W,
                                       const float* __restrict__ convW)
{
    __shared__ float tile[32][33];
    int w = blockIdx.z;
    const float* W = (w == 0) ? fc1W : convW + (size_t)(w - 1) * MM;
    int n0 = blockIdx.x * 32, k0 = blockIdx.y * 32;
    #pragma unroll
    for (int i = 0; i < 32; i += 8)
        tile[threadIdx.y + i][threadIdx.x] = W[(size_t)(k0 + threadIdx.y + i) * NHID + n0 + threadIdx.x];
    __syncthreads();
    #pragma unroll
    for (int i = 0; i < 32; i += 8) {
        float v = tile[threadIdx.x][threadIdx.y + i];
        size_t o = (size_t)w * MM + (size_t)(n0 + threadIdx.y + i) * NHID + k0 + threadIdx.x;
        g_wtf[o] = v;
        if (w == 0) split1(v, g_w0hi[o], g_w0lo[o]);
    }
}

// ---------------------------------------------------------------------------
// Prep: A-factors G1_j=I+λjC1, G3_j=I+λjC3 (+b1/b3 rows), B-factors
// F2_j=(I+λjC2)^T, F4_j=(I+λjC4)^T, and zero Mout.
// ---------------------------------------------------------------------------
#define A_ELEMS (AFAC_ROWS * NHID)
#define B_ELEMS (8 * MM)
#define PREP_TOTAL (A_ELEMS + B_ELEMS + MOUT_ROWS * NHID)

__global__ void prep_kernel(const float* __restrict__ convW,
                            const float* __restrict__ convb)
{
    int idx = blockIdx.x * blockDim.x + threadIdx.x;
    if (idx >= PREP_TOTAL) return;
    const float L[4] = { -1.f / 42.f, 39.f / 42.f, 2.f / 42.f, 1.f };
    if (idx < A_ELEMS) {
        int r = idx >> 9, c = idx & 511;
        float v = 0.f;
        if (r < 2048) {
            int rr = r & 511;
            v = L[r >> 9] * convW[(size_t)rr * NHID + c] + ((rr == c) ? 1.f : 0.f);
        } else if (r < 4096) {
            int r2 = r - 2048, rr = r2 & 511;
            v = L[r2 >> 9] * convW[2 * (size_t)MM + (size_t)rr * NHID + c] + ((rr == c) ? 1.f : 0.f);
        } else if (r == 4096) v = convb[c];
        else if (r == 4224) v = convb[2 * NHID + c];
        split1(v, g_Afhi[idx], g_Aflo[idx]);
    } else if (idx < A_ELEMS + B_ELEMS) {
        int i = idx - A_ELEMS;
        int g = i >> 18;
        int nk = i & (MM - 1);
        int n = nk >> 9, k = nk & 511;
        int j = g & 3;
        int w = (g < 4) ? 2 : 4;          // C2^T or C4^T in wtf
        float v = L[j] * g_wtf[(size_t)w * MM + nk] + ((n == k) ? 1.f : 0.f);
        split1(v, g_Bfhi[i], g_Bflo[i]);
    } else {
        g_Mout[idx - A_ELEMS - B_ELEMS] = 0.f;
    }
}

// ---------------------------------------------------------------------------
// Build node features (f32 for output third) + fp16 hi (x1 GEMM is 1-pass)
// ---------------------------------------------------------------------------
__global__ void build_feats_kernel(const float* __restrict__ a,
                                   const float* __restrict__ v,
                                   const float* __restrict__ l,
                                   const float* __restrict__ qmask,
                                   const float* __restrict__ spk)
{
    int idx = blockIdx.x * blockDim.x + threadIdx.x;
    if (idx >= N_NODE * 128) return;
    int c    = (idx & 127) * 4;
    int node = idx >> 7;
    int dia  = node / ROWS_PER_DIA;
    int r    = node - dia * ROWS_PER_DIA;
    int m    = r / L_DIA;
    int t    = r - m * L_DIA;
    int u    = dia * L_DIA + t;

    float4 val;
    if (m == 0) {
        float q0 = qmask[(t * D_DIA + dia) * 2 + 0];
        float q1 = qmask[(t * D_DIA + dia) * 2 + 1];
        int s = (q1 > q0) ? 1 : 0;
        float4 lv = *(const float4*)(l + (size_t)u * NHID + c);
        float4 sv = *(const float4*)(spk + (size_t)s * NHID + c);
        val = make_float4(lv.x + sv.x, lv.y + sv.y, lv.z + sv.z, lv.w + sv.w);
    } else if (m == 1) {
        val = *(const float4*)(a + (size_t)u * NHID + c);
    } else {
        val = *(const float4*)(v + (size_t)u * NHID + c);
    }
    size_t o = (size_t)node * NHID + c;
    *(float4*)(g_feats + o) = val;
    g_fahi[o]     = __float2half_rn(val.x);
    g_fahi[o + 1] = __float2half_rn(val.y);
    g_fahi[o + 2] = __float2half_rn(val.z);
    g_fahi[o + 3] = __float2half_rn(val.w);
}

// ---------------------------------------------------------------------------
// Misc (one launch): [0,1024) transpose P2_j -> B-splits; [1024,1152) means
// of x1 (fp16 hi only); [1152] dA row = bb1 + b2 -> splits at outA row 4096.
// ---------------------------------------------------------------------------
__global__ void misc_kernel(const float* __restrict__ convb)
{
    __shared__ float tile[32][33];
    int b = blockIdx.x, tid = threadIdx.x;
    if (b < 1024) {
        int z = b >> 8, t = b & 255;
        int r0 = (t >> 4) * 32, c0 = (t & 15) * 32;
        int tx = tid & 31, ty = tid >> 5;
        #pragma unroll
        for (int i = 0; i < 32; i += 8)
            tile[ty + i][tx] = g_outA[(size_t)(2048 + z * 512 + r0 + ty + i) * NHID + c0 + tx];
        __syncthreads();
        #pragma unroll
        for (int i = 0; i < 32; i += 8) {
            size_t o = (size_t)z * MM + (size_t)(c0 + ty + i) * NHID + r0 + tx;
            split1(tile[tx][ty + i], g_P2Thi[o], g_P2Tlo[o]);
        }
    } else if (b < 1152) {
        int dia = b - 1024;
        int c = tid * 2;
        const float* xb = g_outA + (size_t)(X1_BASE + dia * ROWS_PER_DIA) * NHID;
        float s0x = 0, s0y = 0, s1x = 0, s1y = 0, s2x = 0, s2y = 0;
        for (int t = 0; t < L_DIA; t++) {
            float2 v0 = *(const float2*)(xb + (size_t)t * NHID + c);
            float2 v1 = *(const float2*)(xb + (size_t)(L_DIA + t) * NHID + c);
            float2 v2 = *(const float2*)(xb + (size_t)(2 * L_DIA + t) * NHID + c);
            s0x += v0.x; s0y += v0.y;
            s1x += v1.x; s1y += v1.y;
            s2x += v2.x; s2y += v2.y;
            const float i3 = 1.f / 3.f;
            size_t o = ((size_t)dia * L_DIA + t) * NHID + c;
            g_mhi[o]     = __float2half_rn((v0.x + v1.x + v2.x) * i3);
            g_mhi[o + 1] = __float2half_rn((v0.y + v1.y + v2.y) * i3);
        }
        const float i40 = 1.f / 40.f, i120 = 1.f / 120.f;
        size_t ob = (5120 + (size_t)dia * 3) * NHID + c;
        g_mhi[ob]              = __float2half_rn(s0x * i40);
        g_mhi[ob + 1]          = __float2half_rn(s0y * i40);
        g_mhi[ob + NHID]       = __float2half_rn(s1x * i40);
        g_mhi[ob + NHID + 1]   = __float2half_rn(s1y * i40);
        g_mhi[ob + 2*NHID]     = __float2half_rn(s2x * i40);
        g_mhi[ob + 2*NHID + 1] = __float2half_rn(s2y * i40);
        size_t og = (5504 + (size_t)dia) * NHID + c;
        g_mhi[og]     = __float2half_rn((s0x + s1x + s2x) * i120);
        g_mhi[og + 1] = __float2half_rn((s0y + s1y + s2y) * i120);
    } else {
        int c = tid * 2;
        size_t o = (size_t)4096 * NHID + c;
        float2 v  = *(const float2*)(g_outA + o);
        float2 b2 = *(const float2*)(convb + NHID + c);
        split1(v.x + b2.x, g_oAhi[o],     g_oAlo[o]);
        split1(v.y + b2.y, g_oAhi[o + 1], g_oAlo[o + 1]);
    }
}

// ---------------------------------------------------------------------------
// Combos of M_j -> B-format splits; block (0,0,0) also builds dd vector:
// dd = d0 (Mout row 2048) + bb3 (outA row 4224) + b4.
// z0 M0^T; z1 (MT-M0)^T; z2 (MB-M0)^T; z3 (M0-MB-MT+MG)^T
// ---------------------------------------------------------------------------
__global__ void combo_xpose_kernel(const float* __restrict__ convb)
{
    __shared__ float tile[32][33];
    const float CF[4][4] = { {1,0,0,0}, {-1,0,1,0}, {-1,1,0,0}, {1,-1,-1,1} };
    int z = blockIdx.z;
    int c0 = blockIdx.x * 32, r0 = blockIdx.y * 32;
    #pragma unroll
    for (int i = 0; i < 32; i += 8) {
        size_t rc = (size_t)(r0 + threadIdx.y + i) * NHID + c0 + threadIdx.x;
        float v = 0.f;
        #pragma unroll
        for (int j = 0; j < 4; j++)
            if (CF[z][j] != 0.f) v += CF[z][j] * g_Mout[(size_t)j * 512 * NHID + rc];
        tile[threadIdx.y + i][threadIdx.x] = v;
    }
    __syncthreads();
    #pragma unroll
    for (int i = 0; i < 32; i += 8) {
        size_t o = (size_t)z * MM + (size_t)(c0 + threadIdx.y + i) * NHID + r0 + threadIdx.x;
        split1(tile[threadIdx.x][threadIdx.y + i], g_cbhi[o], g_cblo[o]);
    }
    if (z == 0 && blockIdx.x == 0 && blockIdx.y == 0) {
        int t = threadIdx.y * 32 + threadIdx.x;   // 0..255
        #pragma unroll
        for (int i = 0; i < 2; i++) {
            int c = t + i * 256;
            g_ddv[c] = g_Mout[(size_t)2048 * NHID + c]
                     + g_outA[(size_t)4224 * NHID + c]
                     + convb[3 * NHID + c];
        }
    }
}

// ---------------------------------------------------------------------------
extern "C" void kernel_launch(void* const* d_in, const int* in_sizes, int n_in,
                              void* d_out, int out_size)
{
    const float* a      = (const float*)d_in[0];
    const float* v      = (const float*)d_in[1];
    const float* l      = (const float*)d_in[2];
    const float* qmask  = (const float*)d_in[3];
    const float* spk    = (const float*)d_in[4];
    const float* fc1_W  = (const float*)d_in[5];
    const float* fc1_b  = (const float*)d_in[6];
    const float* convW  = (const float*)d_in[7];
    const float* convb  = (const float*)d_in[8];
    float* out = (float*)d_out;

    __half *w0hi, *w0lo, *fahi, *oAhi, *oAlo, *Afhi, *Aflo;
    __half *Bfhi, *Bflo, *P2Thi, *P2Tlo, *mhi, *cbhi, *cblo;
    float *outA, *Mout, *gnn, *feats, *ddv;
    cudaGetSymbolAddress((void**)&w0hi, g_w0hi);   cudaGetSymbolAddress((void**)&w0lo, g_w0lo);
    cudaGetSymbolAddress((void**)&fahi, g_fahi);
    cudaGetSymbolAddress((void**)&oAhi, g_oAhi);   cudaGetSymbolAddress((void**)&oAlo, g_oAlo);
    cudaGetSymbolAddress((void**)&Afhi, g_Afhi);   cudaGetSymbolAddress((void**)&Aflo, g_Aflo);
    cudaGetSymbolAddress((void**)&Bfhi, g_Bfhi);   cudaGetSymbolAddress((void**)&Bflo, g_Bflo);
    cudaGetSymbolAddress((void**)&P2Thi, g_P2Thi); cudaGetSymbolAddress((void**)&P2Tlo, g_P2Tlo);
    cudaGetSymbolAddress((void**)&mhi, g_mhi);
    cudaGetSymbolAddress((void**)&cbhi, g_cbhi);   cudaGetSymbolAddress((void**)&cblo, g_cblo);
    cudaGetSymbolAddress((void**)&outA, g_outA);
    cudaGetSymbolAddress((void**)&Mout, g_Mout);
    cudaGetSymbolAddress((void**)&gnn, g_gnn);
    cudaGetSymbolAddress((void**)&feats, g_feats);
    cudaGetSymbolAddress((void**)&ddv, g_ddv);

    cudaFuncSetAttribute(gemm_u, cudaFuncAttributeMaxDynamicSharedMemorySize, GEMM_SMEM_BYTES);

    const int BIG = 1 << 20;

    // 1. transpose weights; 2. prep factors + zero Mout; 3. features
    transpose_split_kernel<<<dim3(16, 16, 5), dim3(32, 8)>>>(fc1_W, convW);
    prep_kernel<<<(PREP_TOTAL + 255) / 256, 256>>>(convW, convb);
    build_feats_kernel<<<(N_NODE * 128 + 255) / 256, 256>>>(a, v, l, qmask, spk);

    // 4. MEGA-A: products+bias rows (3-pass, y 0..33 — start first) + x1 (1-pass, y 34..153)
    {
        GP p{};
        p.Ahi0 = Afhi; p.Alo0 = Aflo;
        p.Ahi1 = fahi; p.Alo1 = fahi;       // x1 region is 1-pass; Alo unused
        p.aSwitchY = 34; p.aRowOfs0 = 0; p.aRowOfs1 = X1_BASE;
        const int ys[11]   = { 0, 4, 8, 12, 16, 20, 24, 28, 32, 33, 34 };
        const int bofs[11] = { 0, 1, 2, 3, 4, 5, 6, 7, 3, 7, -1 };
        for (int i = 0; i < 11; i++) {
            p.yStart[i] = ys[i];
            p.npass[i] = (i == 10) ? 1 : 3;
            if (i == 10) { p.Bhi[i] = w0hi; p.Blo[i] = w0lo; }
            else         { p.Bhi[i] = Bfhi + (size_t)bofs[i] * MM; p.Blo[i] = Bflo + (size_t)bofs[i] * MM; }
        }
        p.bias[10] = fc1_b;
        p.C = outA; p.Chi = oAhi; p.Clo = oAlo;
        p.loSkipMask = 1 << 10;             // x1 rows: no lo split needed
        gemm_u<<<dim3(4, OUTA_ROWS / 128), 256, GEMM_SMEM_BYTES>>>(p);
    }

    // 5. misc: P2 transpose-splits + means(hi) + dA row
    misc_kernel<<<1153, 256>>>(convb);

    // 6. step B: M_j = P1_j * P2_j and d0 = dA * P2_3  (split-K 3-pass)
    {
        GP p{};
        p.Ahi0 = oAhi; p.Alo0 = oAlo;
        p.Ahi1 = oAhi; p.Alo1 = oAlo;
        p.aSwitchY = 16; p.aRowOfs0 = 0; p.aRowOfs1 = -2048;   // y16: bm=2048 -> row 4096 (dA)
        const int ys[11]   = { 0, 4, 8, 12, 16, BIG, BIG, BIG, BIG, BIG, BIG };
        const int bofs[11] = { 0, 1, 2, 3, 3, 3, 3, 3, 3, 3, 3 };
        for (int i = 0; i < 11; i++) {
            p.yStart[i] = ys[i];
            p.npass[i] = 3;
            p.Bhi[i] = P2Thi + (size_t)bofs[i] * MM;
            p.Blo[i] = P2Tlo + (size_t)bofs[i] * MM;
        }
        p.C = Mout;
        p.splitK = 1;
        gemm_u<<<dim3(4, MOUT_ROWS / 128, 3), 256, GEMM_SMEM_BYTES>>>(p);
    }

    // 7. combos -> B-format (+ dd vector)
    combo_xpose_kernel<<<dim3(16, 16, 4), dim3(32, 8)>>>(convb);

    // 8. G1: means GEMM (ft/fb/fg x combos), 1-pass -> g_gnn
    {
        GP p{};
        p.Ahi0 = mhi; p.Alo0 = mhi;
        p.Ahi1 = mhi; p.Alo1 = mhi;
        p.aSwitchY = BIG;
        const int ys[11] = { 0, 40, 43, BIG, BIG, BIG, BIG, BIG, BIG, BIG, BIG };
        for (int i = 0; i < 11; i++) {
            p.yStart[i] = (i < 3) ? ys[i] : BIG;
            p.npass[i] = 1;
            int bi = (i == 0) ? 1 : (i == 1) ? 2 : 3;
            p.Bhi[i] = cbhi + (size_t)bi * MM;
            p.Blo[i] = cblo + (size_t)bi * MM;
        }
        p.C = gnn;
        gemm_u<<<dim3(4, MEAN_ROWS / 128), 256, GEMM_SMEM_BYTES>>>(p);
    }

    // 9. G2: node GEMM (x1 * M0), 1-pass, fused final-output epilogue
    {
        GP p{};
        p.Ahi0 = oAhi + (size_t)X1_BASE * NHID; p.Alo0 = p.Ahi0;
        p.Ahi1 = p.Ahi0; p.Alo1 = p.Ahi0;
        p.aSwitchY = BIG;
        for (int i = 0; i < 11; i++) {
            p.yStart[i] = (i == 0) ? 0 : BIG;
            p.npass[i] = 1;
            p.Bhi[i] = cbhi;
            p.Blo[i] = cblo;
        }
        p.C = out;
        p.fuse = 1;
        p.gt = gnn;
        p.ddv = ddv;
        p.featsP = feats;
        p.x1P = outA + (size_t)X1_BASE * NHID;
        gemm_u<<<dim3(4, N_NODE / 128), 256, GEMM_SMEM_BYTES>>>(p);
    }

    (void)in_sizes; (void)n_in; (void)out_size;
}